// round 12
// baseline (speedup 1.0000x reference)
#include <cuda_runtime.h>
#include <math.h>

#define NN     50000
#define EE     600000
#define GG     256
#define HID    128
#define EDIM   16
#define EH     64
#define NL     4
#define MINF   200
#define MH     256
#define MOUT   128
#define PH     512
#define PIN    (HID + MOUT)

// ---------------- scratch (static device globals) -------------------------
__device__ float g_w[NL * EE];          // [l][e] edge gates (coalesced by e)
__device__ float g_dinv[NN * NL];       // [n][l]
__device__ float g_h[NN * HID];
__device__ float g_hl[NN * HID];        // hl' = dinv * (h @ lin_W)
__device__ float g_out[NN * HID];       // aggregated S'
__device__ int   g_cnt_csr[NN];
__device__ int   g_ptr[NN + 1];
__device__ int   g_cursor[NN];
__device__ int2  g_se[EE];              // (src, eid) grouped by dst
__device__ int   g_bsum[64];
__device__ int   g_boff[64];
__device__ float g_t0[GG * MH];
__device__ float g_t1[GG * MH];
__device__ float g_cat[GG * PIN];
__device__ float g_p0[GG * PH];
__device__ float g_p1[GG * PH];

// ---------------- CSR build -----------------------------------------------
__global__ void zero_cnt()
{
    int i = blockIdx.x * blockDim.x + threadIdx.x;
    if (i < NN) g_cnt_csr[i] = 0;
}

__global__ void hist(const int* __restrict__ colp)
{
    int e = blockIdx.x * blockDim.x + threadIdx.x;
    if (e < EE) atomicAdd(&g_cnt_csr[colp[e]], 1);
}

__global__ __launch_bounds__(1024) void blockscan()
{
    __shared__ int swsum[32];
    int t = threadIdx.x;
    int i = blockIdx.x * 1024 + t;
    int v = (i < NN) ? g_cnt_csr[i] : 0;
    int lane = t & 31, w = t >> 5;
    int incl = v;
#pragma unroll
    for (int off = 1; off < 32; off <<= 1) {
        int n = __shfl_up_sync(0xFFFFFFFFu, incl, off);
        if (lane >= off) incl += n;
    }
    if (lane == 31) swsum[w] = incl;
    __syncthreads();
    if (w == 0) {
        int s = swsum[lane];
        int si = s;
#pragma unroll
        for (int off = 1; off < 32; off <<= 1) {
            int n = __shfl_up_sync(0xFFFFFFFFu, si, off);
            if (lane >= off) si += n;
        }
        swsum[lane] = si - s;
        if (lane == 31 && blockIdx.x < 64) g_bsum[blockIdx.x] = si;
    }
    __syncthreads();
    int excl = incl - v + swsum[w];
    if (i < NN) g_ptr[i] = excl;
}

__global__ void midscan(int nblk)
{
    __shared__ int s[64];
    int t = threadIdx.x;
    int v = (t < nblk) ? g_bsum[t] : 0;
    s[t] = v;
    __syncthreads();
#pragma unroll
    for (int off = 1; off < 64; off <<= 1) {
        int add = (t >= off) ? s[t - off] : 0;
        __syncthreads();
        s[t] += add;
        __syncthreads();
    }
    g_boff[t] = s[t] - v;
}

__global__ void addoff()
{
    int i = blockIdx.x * blockDim.x + threadIdx.x;
    if (i < NN) {
        int p = g_ptr[i] + g_boff[i >> 10];
        g_ptr[i] = p;
        g_cursor[i] = p;
    }
    if (i == 0) g_ptr[NN] = EE;
}

__global__ void fill_csr(const int* __restrict__ rowp, const int* __restrict__ colp)
{
    int e = blockIdx.x * blockDim.x + threadIdx.x;
    if (e >= EE) return;
    int c = colp[e];
    int pos = atomicAdd(&g_cursor[c], 1);
    g_se[pos] = make_int2(rowp[e], e);
}

// ---------------- edge MLP (R3-proven scalar: 1 edge/thread) --------------
__global__ __launch_bounds__(256) void edge_mlp_all(
    const float* __restrict__ ea, const float* __restrict__ mW1,
    const float* __restrict__ mb1, const float* __restrict__ mW2,
    const float* __restrict__ mb2)
{
    __shared__ float sW1t[NL][EH * EDIM];   // transposed: [l][j][k]
    __shared__ float sb1[NL][EH];
    __shared__ float sW2[NL][EH];
    __shared__ float sb2[NL];
    int t = threadIdx.x;
    for (int i = t; i < NL * EDIM * EH; i += 256) {
        int l = i / (EDIM * EH);
        int rem = i % (EDIM * EH);
        int k = rem / EH, j = rem % EH;      // mW1 is [l][k][j]
        sW1t[l][j * EDIM + k] = mW1[i];
    }
    for (int i = t; i < NL * EH; i += 256) {
        sb1[i / EH][i % EH] = mb1[i];
        sW2[i / EH][i % EH] = mW2[i];
    }
    if (t < NL) sb2[t] = mb2[t];
    __syncthreads();

    int e = blockIdx.x * 256 + t;
    if (e >= EE) return;
    float a[EDIM];
    const float4* eap = (const float4*)(ea + (size_t)e * EDIM);
#pragma unroll
    for (int q = 0; q < 4; q++) {
        float4 v = eap[q];
        a[q * 4 + 0] = v.x; a[q * 4 + 1] = v.y; a[q * 4 + 2] = v.z; a[q * 4 + 3] = v.w;
    }
#pragma unroll 1
    for (int l = 0; l < NL; l++) {
        float acc = sb2[l];
#pragma unroll 4
        for (int j = 0; j < EH; j++) {
            const float4* wp = (const float4*)&sW1t[l][j * EDIM];
            float s = sb1[l][j];
#pragma unroll
            for (int q = 0; q < 4; q++) {
                float4 w4 = wp[q];
                s = fmaf(a[q * 4 + 0], w4.x, s);
                s = fmaf(a[q * 4 + 1], w4.y, s);
                s = fmaf(a[q * 4 + 2], w4.z, s);
                s = fmaf(a[q * 4 + 3], w4.w, s);
            }
            acc = fmaf(fmaxf(s, 0.f), sW2[l][j], acc);
        }
        g_w[l * EE + e] = 1.f / (1.f + __expf(-acc));
    }
}

// ---------------- degree + dinv via CSR (all layers) ----------------------
__global__ void deg_dinv()
{
    int n = blockIdx.x * blockDim.x + threadIdx.x;
    if (n >= NN) return;
    int beg = g_ptr[n], end = g_ptr[n + 1];
    float d0 = 1.f, d1 = 1.f, d2 = 1.f, d3 = 1.f;
    for (int i = beg; i < end; i++) {
        int eid = g_se[i].y;
        d0 += g_w[0 * EE + eid];
        d1 += g_w[1 * EE + eid];
        d2 += g_w[2 * EE + eid];
        d3 += g_w[3 * EE + eid];
    }
    g_dinv[n * NL + 0] = rsqrtf(d0);
    g_dinv[n * NL + 1] = rsqrtf(d1);
    g_dinv[n * NL + 2] = rsqrtf(d2);
    g_dinv[n * NL + 3] = rsqrtf(d3);
}

// ---------------- gather-aggregate: 1 warp per node -----------------------
__global__ __launch_bounds__(256) void agg(const float* __restrict__ w)
{
    int gid = blockIdx.x * 256 + threadIdx.x;
    int n = gid >> 5;
    if (n >= NN) return;
    int lane = gid & 31;
    const float4* hlv = (const float4*)g_hl;
    float4 acc = hlv[(size_t)n * 32 + lane];      // self-loop term = hl'[n]
    int beg = g_ptr[n], end = g_ptr[n + 1];

    if (beg < end) {
        int2 se = __ldg(&g_se[beg]);
        float wt = __ldg(&w[se.y]);
        for (int i = beg; i < end; i++) {
            int2 se_n = make_int2(0, 0); float wt_n = 0.f;
            if (i + 1 < end) {
                se_n = __ldg(&g_se[i + 1]);
                wt_n = __ldg(&w[se_n.y]);
            }
            float4 v = hlv[(size_t)se.x * 32 + lane];
            acc.x = fmaf(wt, v.x, acc.x);
            acc.y = fmaf(wt, v.y, acc.y);
            acc.z = fmaf(wt, v.z, acc.z);
            acc.w = fmaf(wt, v.w, acc.w);
            se = se_n; wt = wt_n;
        }
    }
    ((float4*)g_out)[(size_t)n * 32 + lane] = acc;
}

// ---------------- node matmul (R3-proven): 16 rows x 128 cols, 128 thr ----
__global__ __launch_bounds__(128) void node_mm(
    const float* __restrict__ in, const float* __restrict__ W,
    const float* __restrict__ in_scale, const float* __restrict__ in_bias,
    const float* __restrict__ bias, float* __restrict__ out,
    const float* __restrict__ out_scale, int do_relu)
{
    __shared__ float sin_t[128 * 20];   // [k][row], padded
    const int t = threadIdx.x;
    const int base = blockIdx.x * 16;
    for (int idx = t; idx < 16 * 128; idx += 128) {
        int row = idx >> 7, k = idx & 127;
        int grow = base + row;
        float v = 0.f;
        if (grow < NN) {
            v = in[(size_t)grow * HID + k];
            if (in_scale) v = fmaf(v, in_scale[(size_t)grow * NL], in_bias[k]);
        }
        sin_t[k * 20 + row] = v;
    }
    __syncthreads();

    const int cx = t & 31;
    const int ry = t >> 5;
    float acc[4][4];
    float4 bv = bias ? *(const float4*)&bias[cx * 4] : make_float4(0.f, 0.f, 0.f, 0.f);
#pragma unroll
    for (int r = 0; r < 4; r++) {
        acc[r][0] = bv.x; acc[r][1] = bv.y; acc[r][2] = bv.z; acc[r][3] = bv.w;
    }
#pragma unroll 8
    for (int k = 0; k < 128; k++) {
        float4 wv = *(const float4*)&W[(size_t)k * HID + cx * 4];
        float4 iv = *(const float4*)&sin_t[k * 20 + ry * 4];
        acc[0][0] = fmaf(iv.x, wv.x, acc[0][0]); acc[0][1] = fmaf(iv.x, wv.y, acc[0][1]);
        acc[0][2] = fmaf(iv.x, wv.z, acc[0][2]); acc[0][3] = fmaf(iv.x, wv.w, acc[0][3]);
        acc[1][0] = fmaf(iv.y, wv.x, acc[1][0]); acc[1][1] = fmaf(iv.y, wv.y, acc[1][1]);
        acc[1][2] = fmaf(iv.y, wv.z, acc[1][2]); acc[1][3] = fmaf(iv.y, wv.w, acc[1][3]);
        acc[2][0] = fmaf(iv.z, wv.x, acc[2][0]); acc[2][1] = fmaf(iv.z, wv.y, acc[2][1]);
        acc[2][2] = fmaf(iv.z, wv.z, acc[2][2]); acc[2][3] = fmaf(iv.z, wv.w, acc[2][3]);
        acc[3][0] = fmaf(iv.w, wv.x, acc[3][0]); acc[3][1] = fmaf(iv.w, wv.y, acc[3][1]);
        acc[3][2] = fmaf(iv.w, wv.z, acc[3][2]); acc[3][3] = fmaf(iv.w, wv.w, acc[3][3]);
    }
#pragma unroll
    for (int r = 0; r < 4; r++) {
        int grow = base + ry * 4 + r;
        if (grow < NN) {
            float os = out_scale ? out_scale[(size_t)grow * NL] : 1.f;
            float4 o = make_float4(acc[r][0] * os, acc[r][1] * os,
                                   acc[r][2] * os, acc[r][3] * os);
            if (do_relu) {
                o.x = fmaxf(o.x, 0.f); o.y = fmaxf(o.y, 0.f);
                o.z = fmaxf(o.z, 0.f); o.w = fmaxf(o.w, 0.f);
            }
            *(float4*)&out[(size_t)grow * HID + cx * 4] = o;
        }
    }
}

// ---------------- fused layer-boundary matmul -----------------------------
// hl_out = dinv_next * ( relu( (S*dinv_l + cbias_l) @ gcnW + gcnb ) @ linW )
__global__ __launch_bounds__(128) void fused_mm(
    const float* __restrict__ S, const float* __restrict__ dinv_l,
    const float* __restrict__ cbias_l,
    const float* __restrict__ gcnW, const float* __restrict__ gcnb,
    const float* __restrict__ linW, const float* __restrict__ dinv_next,
    float* __restrict__ hl_out)
{
    __shared__ float sin_t[128 * 20];   // [k][row]
    const int t = threadIdx.x;
    const int base = blockIdx.x * 16;
    for (int idx = t; idx < 16 * 128; idx += 128) {
        int row = idx >> 7, k = idx & 127;
        int grow = base + row;
        float v = 0.f;
        if (grow < NN)
            v = fmaf(S[(size_t)grow * HID + k], dinv_l[(size_t)grow * NL], cbias_l[k]);
        sin_t[k * 20 + row] = v;
    }
    __syncthreads();

    const int cx = t & 31;
    const int ry = t >> 5;

    // ---- stage 1: h = relu(tile @ gcnW + gcnb) ----
    float acc[4][4];
    {
        float4 bv = *(const float4*)&gcnb[cx * 4];
#pragma unroll
        for (int r = 0; r < 4; r++) {
            acc[r][0] = bv.x; acc[r][1] = bv.y; acc[r][2] = bv.z; acc[r][3] = bv.w;
        }
    }
#pragma unroll 8
    for (int k = 0; k < 128; k++) {
        float4 wv = *(const float4*)&gcnW[(size_t)k * HID + cx * 4];
        float4 iv = *(const float4*)&sin_t[k * 20 + ry * 4];
        acc[0][0] = fmaf(iv.x, wv.x, acc[0][0]); acc[0][1] = fmaf(iv.x, wv.y, acc[0][1]);
        acc[0][2] = fmaf(iv.x, wv.z, acc[0][2]); acc[0][3] = fmaf(iv.x, wv.w, acc[0][3]);
        acc[1][0] = fmaf(iv.y, wv.x, acc[1][0]); acc[1][1] = fmaf(iv.y, wv.y, acc[1][1]);
        acc[1][2] = fmaf(iv.y, wv.z, acc[1][2]); acc[1][3] = fmaf(iv.y, wv.w, acc[1][3]);
        acc[2][0] = fmaf(iv.z, wv.x, acc[2][0]); acc[2][1] = fmaf(iv.z, wv.y, acc[2][1]);
        acc[2][2] = fmaf(iv.z, wv.z, acc[2][2]); acc[2][3] = fmaf(iv.z, wv.w, acc[2][3]);
        acc[3][0] = fmaf(iv.w, wv.x, acc[3][0]); acc[3][1] = fmaf(iv.w, wv.y, acc[3][1]);
        acc[3][2] = fmaf(iv.w, wv.z, acc[3][2]); acc[3][3] = fmaf(iv.w, wv.w, acc[3][3]);
    }
    __syncthreads();

    // write relu(h) back transposed into sin_t
#pragma unroll
    for (int r = 0; r < 4; r++) {
        int row = ry * 4 + r;
#pragma unroll
        for (int c = 0; c < 4; c++) {
            sin_t[(cx * 4 + c) * 20 + row] = fmaxf(acc[r][c], 0.f);
        }
    }
    __syncthreads();

    // ---- stage 2: hl = dinv_next * (h @ linW) ----
    float acc2[4][4];
#pragma unroll
    for (int r = 0; r < 4; r++) {
        acc2[r][0] = 0.f; acc2[r][1] = 0.f; acc2[r][2] = 0.f; acc2[r][3] = 0.f;
    }
#pragma unroll 8
    for (int k = 0; k < 128; k++) {
        float4 wv = *(const float4*)&linW[(size_t)k * HID + cx * 4];
        float4 iv = *(const float4*)&sin_t[k * 20 + ry * 4];
        acc2[0][0] = fmaf(iv.x, wv.x, acc2[0][0]); acc2[0][1] = fmaf(iv.x, wv.y, acc2[0][1]);
        acc2[0][2] = fmaf(iv.x, wv.z, acc2[0][2]); acc2[0][3] = fmaf(iv.x, wv.w, acc2[0][3]);
        acc2[1][0] = fmaf(iv.y, wv.x, acc2[1][0]); acc2[1][1] = fmaf(iv.y, wv.y, acc2[1][1]);
        acc2[1][2] = fmaf(iv.y, wv.z, acc2[1][2]); acc2[1][3] = fmaf(iv.y, wv.w, acc2[1][3]);
        acc2[2][0] = fmaf(iv.z, wv.x, acc2[2][0]); acc2[2][1] = fmaf(iv.z, wv.y, acc2[2][1]);
        acc2[2][2] = fmaf(iv.z, wv.z, acc2[2][2]); acc2[2][3] = fmaf(iv.z, wv.w, acc2[2][3]);
        acc2[3][0] = fmaf(iv.w, wv.x, acc2[3][0]); acc2[3][1] = fmaf(iv.w, wv.y, acc2[3][1]);
        acc2[3][2] = fmaf(iv.w, wv.z, acc2[3][2]); acc2[3][3] = fmaf(iv.w, wv.w, acc2[3][3]);
    }
#pragma unroll
    for (int r = 0; r < 4; r++) {
        int grow = base + ry * 4 + r;
        if (grow < NN) {
            float os = dinv_next[(size_t)grow * NL];
            float4 o = make_float4(acc2[r][0] * os, acc2[r][1] * os,
                                   acc2[r][2] * os, acc2[r][3] * os);
            *(float4*)&hl_out[(size_t)grow * HID + cx * 4] = o;
        }
    }
}

// ---------------- segment-mean pool -> writes into g_cat left half --------
__global__ __launch_bounds__(128) void pool_seg(const int* __restrict__ batch)
{
    __shared__ int sbound[2];
    int g = blockIdx.x, t = threadIdx.x;
    if (t == 0) {
        int lo = 0, hi = NN;
        while (lo < hi) { int m = (lo + hi) >> 1; if (batch[m] < g) lo = m + 1; else hi = m; }
        sbound[0] = lo;
        int lo2 = lo; hi = NN;
        while (lo2 < hi) { int m = (lo2 + hi) >> 1; if (batch[m] < g + 1) lo2 = m + 1; else hi = m; }
        sbound[1] = lo2;
    }
    __syncthreads();
    int beg = sbound[0], end = sbound[1];
    float acc = 0.f;
    for (int n = beg; n < end; n++) acc += g_h[(size_t)n * HID + t];
    float cnt = (float)(end - beg);
    g_cat[(size_t)g * PIN + t] = acc / fmaxf(cnt, 1.f);
}

// ---------------- batched tail GEMM: 32 rows x 64 cols per block ----------
// out row stride = out_stride (enables writing directly into g_cat halves)
__global__ __launch_bounds__(256) void dense_mr(
    const float* __restrict__ in, const float* __restrict__ W,
    const float* __restrict__ b, float* __restrict__ out,
    int K, int Nout, int out_stride, int do_relu)
{
    __shared__ float sin[32 * 129];
    const int t = threadIdx.x;
    const int rbase = blockIdx.y * 32;
    const int cbase = blockIdx.x * 64;
    const int cx = t & 15;
    const int ry = t >> 4;
    float acc[2][4];
    {
        float4 bv = *(const float4*)&b[cbase + cx * 4];
#pragma unroll
        for (int r = 0; r < 2; r++) {
            acc[r][0] = bv.x; acc[r][1] = bv.y; acc[r][2] = bv.z; acc[r][3] = bv.w;
        }
    }
    for (int k0 = 0; k0 < K; k0 += 128) {
        int klen = K - k0 < 128 ? K - k0 : 128;
#pragma unroll
        for (int it = 0; it < 4; it++) {
            int idx4 = t + it * 256;
            int row = idx4 >> 5;
            int k4 = idx4 & 31;
            float4 v = make_float4(0.f, 0.f, 0.f, 0.f);
            if (k4 * 4 < klen) {
                const float* src = &in[(size_t)(rbase + row) * K + k0 + k4 * 4];
                v.x = src[0];
                v.y = (k4 * 4 + 1 < klen) ? src[1] : 0.f;
                v.z = (k4 * 4 + 2 < klen) ? src[2] : 0.f;
                v.w = (k4 * 4 + 3 < klen) ? src[3] : 0.f;
            }
            sin[row * 129 + k4 * 4 + 0] = v.x;
            sin[row * 129 + k4 * 4 + 1] = v.y;
            sin[row * 129 + k4 * 4 + 2] = v.z;
            sin[row * 129 + k4 * 4 + 3] = v.w;
        }
        __syncthreads();
        for (int kk = 0; kk < klen; kk++) {
            float4 wv = *(const float4*)&W[(size_t)(k0 + kk) * Nout + cbase + cx * 4];
            float i0 = sin[(ry * 2 + 0) * 129 + kk];
            float i1 = sin[(ry * 2 + 1) * 129 + kk];
            acc[0][0] = fmaf(i0, wv.x, acc[0][0]); acc[0][1] = fmaf(i0, wv.y, acc[0][1]);
            acc[0][2] = fmaf(i0, wv.z, acc[0][2]); acc[0][3] = fmaf(i0, wv.w, acc[0][3]);
            acc[1][0] = fmaf(i1, wv.x, acc[1][0]); acc[1][1] = fmaf(i1, wv.y, acc[1][1]);
            acc[1][2] = fmaf(i1, wv.z, acc[1][2]); acc[1][3] = fmaf(i1, wv.w, acc[1][3]);
        }
        __syncthreads();
    }
#pragma unroll
    for (int r = 0; r < 2; r++) {
        float4 o = make_float4(acc[r][0], acc[r][1], acc[r][2], acc[r][3]);
        if (do_relu) {
            o.x = fmaxf(o.x, 0.f); o.y = fmaxf(o.y, 0.f);
            o.z = fmaxf(o.z, 0.f); o.w = fmaxf(o.w, 0.f);
        }
        *(float4*)&out[(size_t)(rbase + ry * 2 + r) * out_stride + cbase + cx * 4] = o;
    }
}

__global__ __launch_bounds__(128) void final_out(
    const float* __restrict__ W, const float* __restrict__ b,
    float* __restrict__ out)
{
    int g = blockIdx.x, t = threadIdx.x;
    float acc = 0.f;
    for (int k = t; k < PH; k += 128) acc = fmaf(g_p1[(size_t)g * PH + k], W[k], acc);
#pragma unroll
    for (int off = 16; off; off >>= 1) acc += __shfl_xor_sync(0xFFFFFFFFu, acc, off);
    __shared__ float s[4];
    if ((t & 31) == 0) s[t >> 5] = acc;
    __syncthreads();
    if (t == 0) out[g] = s[0] + s[1] + s[2] + s[3] + b[0];
}

// ---------------- launch --------------------------------------------------
extern "C" void kernel_launch(void* const* d_in, const int* in_sizes, int n_in,
                              void* d_out, int out_size)
{
    const float* x     = (const float*)d_in[0];
    const int*   ei    = (const int*)d_in[1];
    const float* ea    = (const float*)d_in[2];
    const int*   batch = (const int*)d_in[3];
    const float* mol   = (const float*)d_in[4];
    const float* clinW = (const float*)d_in[5];
    const float* cmW1  = (const float*)d_in[6];
    const float* cmb1  = (const float*)d_in[7];
    const float* cmW2  = (const float*)d_in[8];
    const float* cmb2  = (const float*)d_in[9];
    const float* cbias = (const float*)d_in[10];
    const float* gcnW  = (const float*)d_in[11];
    const float* gcnb  = (const float*)d_in[12];
    const float* mW0 = (const float*)d_in[13]; const float* mb0 = (const float*)d_in[14];
    const float* mW1 = (const float*)d_in[15]; const float* mb1 = (const float*)d_in[16];
    const float* mW2 = (const float*)d_in[17]; const float* mb2 = (const float*)d_in[18];
    const float* mW3 = (const float*)d_in[19]; const float* mb3 = (const float*)d_in[20];
    const float* pW0 = (const float*)d_in[21]; const float* pb0 = (const float*)d_in[22];
    const float* pW1 = (const float*)d_in[23]; const float* pb1 = (const float*)d_in[24];
    const float* oW  = (const float*)d_in[25]; const float* ob  = (const float*)d_in[26];
    float* out = (float*)d_out;

    const int* rowp = ei;
    const int* colp = ei + EE;

    static float *h_ptr = nullptr, *hl_ptr = nullptr, *out_ptr = nullptr;
    static float *w_ptr = nullptr, *dinv_ptr = nullptr;
    static float *t0_p = nullptr, *t1_p = nullptr;
    static float *cat_p = nullptr, *p0_p = nullptr, *p1_p = nullptr;
    if (!h_ptr) {
        cudaGetSymbolAddress((void**)&h_ptr, g_h);
        cudaGetSymbolAddress((void**)&hl_ptr, g_hl);
        cudaGetSymbolAddress((void**)&out_ptr, g_out);
        cudaGetSymbolAddress((void**)&w_ptr, g_w);
        cudaGetSymbolAddress((void**)&dinv_ptr, g_dinv);
        cudaGetSymbolAddress((void**)&t0_p, g_t0);
        cudaGetSymbolAddress((void**)&t1_p, g_t1);
        cudaGetSymbolAddress((void**)&cat_p, g_cat);
        cudaGetSymbolAddress((void**)&p0_p, g_p0);
        cudaGetSymbolAddress((void**)&p1_p, g_p1);
    }

    // ---- CSR by destination ----
    const int nblk = (NN + 1023) / 1024;
    zero_cnt<<<(NN + 255) / 256, 256>>>();
    hist<<<(EE + 255) / 256, 256>>>(colp);
    blockscan<<<nblk, 1024>>>();
    midscan<<<1, 64>>>(nblk);
    addoff<<<(NN + 255) / 256, 256>>>();
    fill_csr<<<(EE + 255) / 256, 256>>>(rowp, colp);

    // edge gates (coalesced by eid, scalar) + degree norms
    edge_mlp_all<<<(EE + 255) / 256, 256>>>(ea, cmW1, cmb1, cmW2, cmb2);
    deg_dinv<<<(NN + 255) / 256, 256>>>();

    const int mm_grid = (NN + 15) / 16;

    // hl0 = dinv0 * (x @ linW0)
    node_mm<<<mm_grid, 128>>>(x, clinW, nullptr, nullptr, nullptr,
                              hl_ptr, dinv_ptr + 0, 0);
    for (int l = 0; l < NL; l++) {
        agg<<<(NN * 32 + 255) / 256, 256>>>(w_ptr + (size_t)l * EE);
        if (l < NL - 1) {
            fused_mm<<<mm_grid, 128>>>(out_ptr, dinv_ptr + l,
                                       cbias + (size_t)l * HID,
                                       gcnW + (size_t)l * HID * HID,
                                       gcnb + (size_t)l * HID,
                                       clinW + (size_t)(l + 1) * HID * HID,
                                       dinv_ptr + (l + 1), hl_ptr);
        } else {
            node_mm<<<mm_grid, 128>>>(out_ptr, gcnW + (size_t)l * HID * HID,
                                      dinv_ptr + l, cbias + (size_t)l * HID,
                                      gcnb + (size_t)l * HID, h_ptr, nullptr, 1);
        }
    }

    pool_seg<<<GG, 128>>>(batch);   // writes g_cat[:, 0:128]

    // mol MLP; final layer writes directly into g_cat[:, 128:256]
    dense_mr<<<dim3(MH / 64, 8), 256>>>(mol,  mW0, mb0, t0_p, MINF, MH, MH, 1);
    dense_mr<<<dim3(MH / 64, 8), 256>>>(t0_p, mW1, mb1, t1_p, MH,   MH, MH, 1);
    dense_mr<<<dim3(MH / 64, 8), 256>>>(t1_p, mW2, mb2, t0_p, MH,   MH, MH, 1);
    dense_mr<<<dim3(MOUT / 64, 8), 256>>>(t0_p, mW3, mb3, cat_p + HID, MH, MOUT, PIN, 1);

    dense_mr<<<dim3(PH / 64, 8), 256>>>(cat_p, pW0, pb0, p0_p, PIN, PH, PH, 1);
    dense_mr<<<dim3(PH / 64, 8), 256>>>(p0_p,  pW1, pb1, p1_p, PH,  PH, PH, 1);
    final_out<<<GG, 128>>>(oW, ob, out);
}

// round 13
// speedup vs baseline: 1.3248x; 1.3248x over previous
#include <cuda_runtime.h>
#include <math.h>
#include <stdint.h>

#define NN     50000
#define EE     600000
#define GG     256
#define HID    128
#define EDIM   16
#define EH     64
#define NL     4
#define MINF   200
#define MH     256
#define MOUT   128
#define PH     512
#define PIN    (HID + MOUT)

#define SA 132          // A_s row stride (floats) — conflict-free fragment reads
#define SB 136          // B_s row stride (floats) — conflict-free fragment reads

typedef unsigned long long ull;

// ---------------- scratch (static device globals) -------------------------
__device__ float    g_w[NL * EE];       // [l][e] edge gates
__device__ float    g_dinv[NN * NL];    // [n][l]
__device__ float    g_h[NN * HID];
__device__ float    g_hl[NN * HID];
__device__ float    g_out[NN * HID];
__device__ unsigned g_Wtf[2 * NL * HID * HID];  // tf32 weights: [lin(0..3), gcn(0..3)]
__device__ int      g_cnt_csr[NN];
__device__ int      g_ptr[NN + 1];
__device__ int      g_cursor[NN];
__device__ int2     g_se[EE];
__device__ int      g_bsum[64];
__device__ int      g_boff[64];
__device__ float    g_t0[GG * MH];
__device__ float    g_t1[GG * MH];
__device__ float    g_cat[GG * PIN];
__device__ float    g_p0[GG * PH];
__device__ float    g_p1[GG * PH];

// ---------------- helpers -------------------------------------------------
__device__ __forceinline__ ull pack2(float a, float b)
{
    ull r; asm("mov.b64 %0, {%1, %2};" : "=l"(r) : "f"(a), "f"(b)); return r;
}
__device__ __forceinline__ void unpack2(ull p, float& a, float& b)
{
    asm("mov.b64 {%0, %1}, %2;" : "=f"(a), "=f"(b) : "l"(p));
}
#define FMA2(d, a, b, c) \
    asm("fma.rn.f32x2 %0, %1, %2, %3;" : "=l"(d) : "l"(a), "l"(b), "l"(c))

__device__ __forceinline__ unsigned f2tf(float f)
{
    unsigned u; asm("cvt.rna.tf32.f32 %0, %1;" : "=r"(u) : "f"(f)); return u;
}

__device__ __forceinline__ void mma_tf32(float* d,
    unsigned a0, unsigned a1, unsigned a2, unsigned a3,
    unsigned b0, unsigned b1)
{
    asm("mma.sync.aligned.m16n8k8.row.col.f32.tf32.tf32.f32 "
        "{%0,%1,%2,%3}, {%4,%5,%6,%7}, {%8,%9}, {%0,%1,%2,%3};"
        : "+f"(d[0]), "+f"(d[1]), "+f"(d[2]), "+f"(d[3])
        : "r"(a0), "r"(a1), "r"(a2), "r"(a3), "r"(b0), "r"(b1));
}

// shared 16x128 @ K=128 tf32 GEMM core (A in A_s, W tf32 in gmem, B_s scratch)
__device__ __forceinline__ void gemm_16x128(
    const unsigned* __restrict__ A_s, unsigned* __restrict__ B_s,
    const unsigned* __restrict__ W, float d[4][4], int t, int lane, int warp)
{
    const int g = lane >> 2, tg = lane & 3;
    const int nb = warp * 32;
#pragma unroll
    for (int kc = 0; kc < 4; kc++) {
        __syncthreads();
        // stage B chunk: rows kc*32..+31, all 128 cols (coalesced uint4)
#pragma unroll
        for (int it = 0; it < 8; it++) {
            int idx4 = t + it * 128;
            int r = idx4 >> 5, c4 = idx4 & 31;
            uint4 wv = *(const uint4*)&W[(size_t)(kc * 32 + r) * HID + c4 * 4];
            *(uint4*)&B_s[r * SB + c4 * 4] = wv;
        }
        __syncthreads();
#pragma unroll
        for (int ks = 0; ks < 4; ks++) {
            int K0 = kc * 32 + ks * 8;   // global k
            int kb = ks * 8;             // chunk-local k
            unsigned a0 = A_s[g * SA + K0 + tg];
            unsigned a1 = A_s[(g + 8) * SA + K0 + tg];
            unsigned a2 = A_s[g * SA + K0 + tg + 4];
            unsigned a3 = A_s[(g + 8) * SA + K0 + tg + 4];
#pragma unroll
            for (int nt = 0; nt < 4; nt++) {
                unsigned b0 = B_s[(kb + tg) * SB + nb + nt * 8 + g];
                unsigned b1 = B_s[(kb + tg + 4) * SB + nb + nt * 8 + g];
                mma_tf32(d[nt], a0, a1, a2, a3, b0, b1);
            }
        }
    }
}

// ---------------- weight conversion to tf32 -------------------------------
__global__ void cvt_weights(const float* __restrict__ linW,
                            const float* __restrict__ gcnW)
{
    int i = blockIdx.x * 256 + threadIdx.x;
    if (i < NL * HID * HID) {
        g_Wtf[i] = f2tf(linW[i]);
        g_Wtf[NL * HID * HID + i] = f2tf(gcnW[i]);
    }
}

// ---------------- CSR build -----------------------------------------------
__global__ void zero_cnt()
{
    int i = blockIdx.x * blockDim.x + threadIdx.x;
    if (i < NN) g_cnt_csr[i] = 0;
}

__global__ void hist(const int* __restrict__ colp)
{
    int e = blockIdx.x * blockDim.x + threadIdx.x;
    if (e < EE) atomicAdd(&g_cnt_csr[colp[e]], 1);
}

__global__ __launch_bounds__(1024) void blockscan()
{
    __shared__ int swsum[32];
    int t = threadIdx.x;
    int i = blockIdx.x * 1024 + t;
    int v = (i < NN) ? g_cnt_csr[i] : 0;
    int lane = t & 31, w = t >> 5;
    int incl = v;
#pragma unroll
    for (int off = 1; off < 32; off <<= 1) {
        int n = __shfl_up_sync(0xFFFFFFFFu, incl, off);
        if (lane >= off) incl += n;
    }
    if (lane == 31) swsum[w] = incl;
    __syncthreads();
    if (w == 0) {
        int s = swsum[lane];
        int si = s;
#pragma unroll
        for (int off = 1; off < 32; off <<= 1) {
            int n = __shfl_up_sync(0xFFFFFFFFu, si, off);
            if (lane >= off) si += n;
        }
        swsum[lane] = si - s;
        if (lane == 31 && blockIdx.x < 64) g_bsum[blockIdx.x] = si;
    }
    __syncthreads();
    int excl = incl - v + swsum[w];
    if (i < NN) g_ptr[i] = excl;
}

__global__ void midscan(int nblk)
{
    __shared__ int s[64];
    int t = threadIdx.x;
    int v = (t < nblk) ? g_bsum[t] : 0;
    s[t] = v;
    __syncthreads();
#pragma unroll
    for (int off = 1; off < 64; off <<= 1) {
        int add = (t >= off) ? s[t - off] : 0;
        __syncthreads();
        s[t] += add;
        __syncthreads();
    }
    g_boff[t] = s[t] - v;
}

__global__ void addoff()
{
    int i = blockIdx.x * blockDim.x + threadIdx.x;
    if (i < NN) {
        int p = g_ptr[i] + g_boff[i >> 10];
        g_ptr[i] = p;
        g_cursor[i] = p;
    }
    if (i == 0) g_ptr[NN] = EE;
}

__global__ void fill_csr(const int* __restrict__ rowp, const int* __restrict__ colp)
{
    int e = blockIdx.x * blockDim.x + threadIdx.x;
    if (e >= EE) return;
    int c = colp[e];
    int pos = atomicAdd(&g_cursor[c], 1);
    g_se[pos] = make_int2(rowp[e], e);
}

// ---------------- edge MLP: 2 edges/thread, f32x2 packed ------------------
__global__ __launch_bounds__(256) void edge_mlp_all(
    const float* __restrict__ ea, const float* __restrict__ mW1,
    const float* __restrict__ mb1, const float* __restrict__ mW2,
    const float* __restrict__ mb2)
{
    __shared__ ull   sW1p[NL][EH * EDIM];
    __shared__ ull   sb1p[NL][EH];
    __shared__ float sW2[NL][EH];
    __shared__ float sb2[NL];
    int t = threadIdx.x;
    for (int i = t; i < NL * EDIM * EH; i += 256) {
        int l = i / (EDIM * EH);
        int rem = i % (EDIM * EH);
        int k = rem / EH, j = rem % EH;
        float w = mW1[i];
        sW1p[l][j * EDIM + k] = pack2(w, w);
    }
    for (int i = t; i < NL * EH; i += 256) {
        float b = mb1[i];
        sb1p[i / EH][i % EH] = pack2(b, b);
        sW2[i / EH][i % EH] = mW2[i];
    }
    if (t < NL) sb2[t] = mb2[t];
    __syncthreads();

    int gid = blockIdx.x * 256 + t;
    if (gid >= EE / 2) return;
    int e0 = gid * 2;

    ull ap[EDIM];
    {
        const float4* p0 = (const float4*)(ea + (size_t)e0 * EDIM);
        const float4* p1 = (const float4*)(ea + (size_t)(e0 + 1) * EDIM);
#pragma unroll
        for (int q = 0; q < 4; q++) {
            float4 a0 = p0[q], a1 = p1[q];
            ap[q * 4 + 0] = pack2(a0.x, a1.x);
            ap[q * 4 + 1] = pack2(a0.y, a1.y);
            ap[q * 4 + 2] = pack2(a0.z, a1.z);
            ap[q * 4 + 3] = pack2(a0.w, a1.w);
        }
    }

#pragma unroll 1
    for (int l = 0; l < NL; l++) {
        float acc0 = sb2[l], acc1 = acc0;
#pragma unroll 2
        for (int j = 0; j < EH; j++) {
            const ull* wp = &sW1p[l][j * EDIM];
            ull sa = sb1p[l][j];
            ull sb = pack2(0.f, 0.f);
#pragma unroll
            for (int k = 0; k < EDIM; k += 2) {
                FMA2(sa, ap[k + 0], wp[k + 0], sa);
                FMA2(sb, ap[k + 1], wp[k + 1], sb);
            }
            float s0a, s1a, s0b, s1b;
            unpack2(sa, s0a, s1a);
            unpack2(sb, s0b, s1b);
            float w2 = sW2[l][j];
            acc0 = fmaf(fmaxf(s0a + s0b, 0.f), w2, acc0);
            acc1 = fmaf(fmaxf(s1a + s1b, 0.f), w2, acc1);
        }
        float2 o;
        o.x = 1.f / (1.f + __expf(-acc0));
        o.y = 1.f / (1.f + __expf(-acc1));
        ((float2*)(g_w + (size_t)l * EE))[gid] = o;
    }
}

// ---------------- degree + dinv via CSR -----------------------------------
__global__ void deg_dinv()
{
    int n = blockIdx.x * blockDim.x + threadIdx.x;
    if (n >= NN) return;
    int beg = g_ptr[n], end = g_ptr[n + 1];
    float d0 = 1.f, d1 = 1.f, d2 = 1.f, d3 = 1.f;
    for (int i = beg; i < end; i++) {
        int eid = g_se[i].y;
        d0 += g_w[0 * EE + eid];
        d1 += g_w[1 * EE + eid];
        d2 += g_w[2 * EE + eid];
        d3 += g_w[3 * EE + eid];
    }
    g_dinv[n * NL + 0] = rsqrtf(d0);
    g_dinv[n * NL + 1] = rsqrtf(d1);
    g_dinv[n * NL + 2] = rsqrtf(d2);
    g_dinv[n * NL + 3] = rsqrtf(d3);
}

// ---------------- gather-aggregate: 1 warp per node -----------------------
__global__ __launch_bounds__(256) void agg(const float* __restrict__ w)
{
    int gid = blockIdx.x * 256 + threadIdx.x;
    int n = gid >> 5;
    if (n >= NN) return;
    int lane = gid & 31;
    const float4* hlv = (const float4*)g_hl;
    float4 acc = hlv[(size_t)n * 32 + lane];
    int beg = g_ptr[n], end = g_ptr[n + 1];

    if (beg < end) {
        int2 se = __ldg(&g_se[beg]);
        float wt = __ldg(&w[se.y]);
        for (int i = beg; i < end; i++) {
            int2 se_n = make_int2(0, 0); float wt_n = 0.f;
            if (i + 1 < end) {
                se_n = __ldg(&g_se[i + 1]);
                wt_n = __ldg(&w[se_n.y]);
            }
            float4 v = hlv[(size_t)se.x * 32 + lane];
            acc.x = fmaf(wt, v.x, acc.x);
            acc.y = fmaf(wt, v.y, acc.y);
            acc.z = fmaf(wt, v.z, acc.z);
            acc.w = fmaf(wt, v.w, acc.w);
            se = se_n; wt = wt_n;
        }
    }
    ((float4*)g_out)[(size_t)n * 32 + lane] = acc;
}

// ---------------- tf32 node matmul: 16 rows x 128 cols, 128 thr -----------
// out = post( out_scale[row] * ( (in*in_scale[row] + in_bias) @ W ) + bias )
__global__ __launch_bounds__(128) void node_mm_tc(
    const float* __restrict__ in, const unsigned* __restrict__ Wtf,
    const float* __restrict__ in_scale, const float* __restrict__ in_bias,
    const float* __restrict__ bias, float* __restrict__ out,
    const float* __restrict__ out_scale, int do_relu)
{
    __shared__ unsigned A_s[16 * SA];
    __shared__ unsigned B_s[32 * SB];
    const int t = threadIdx.x;
    const int base = blockIdx.x * 16;   // NN % 16 == 0

    // stage A (fp32 -> tf32)
#pragma unroll
    for (int it = 0; it < 4; it++) {
        int idx4 = t + it * 128;
        int row = idx4 >> 5, k4 = idx4 & 31;
        int grow = base + row;
        float4 v = *(const float4*)&in[(size_t)grow * HID + k4 * 4];
        if (in_scale) {
            float s = in_scale[(size_t)grow * NL];
            v.x = fmaf(v.x, s, in_bias[k4 * 4 + 0]);
            v.y = fmaf(v.y, s, in_bias[k4 * 4 + 1]);
            v.z = fmaf(v.z, s, in_bias[k4 * 4 + 2]);
            v.w = fmaf(v.w, s, in_bias[k4 * 4 + 3]);
        }
        A_s[row * SA + k4 * 4 + 0] = f2tf(v.x);
        A_s[row * SA + k4 * 4 + 1] = f2tf(v.y);
        A_s[row * SA + k4 * 4 + 2] = f2tf(v.z);
        A_s[row * SA + k4 * 4 + 3] = f2tf(v.w);
    }

    const int lane = t & 31, warp = t >> 5;
    const int g = lane >> 2, tg = lane & 3;
    const int nb = warp * 32;

    float d[4][4];
#pragma unroll
    for (int nt = 0; nt < 4; nt++) {
        float c0 = 0.f, c1 = 0.f;
        if (bias) {
            c0 = bias[nb + nt * 8 + 2 * tg];
            c1 = bias[nb + nt * 8 + 2 * tg + 1];
        }
        d[nt][0] = c0; d[nt][1] = c1; d[nt][2] = c0; d[nt][3] = c1;
    }

    gemm_16x128(A_s, B_s, Wtf, d, t, lane, warp);

    int row0 = base + g, row1 = row0 + 8;
    float s0 = out_scale ? out_scale[(size_t)row0 * NL] : 1.f;
    float s1 = out_scale ? out_scale[(size_t)row1 * NL] : 1.f;
#pragma unroll
    for (int nt = 0; nt < 4; nt++) {
        int col = nb + nt * 8 + 2 * tg;
        float2 o0 = make_float2(d[nt][0] * s0, d[nt][1] * s0);
        float2 o1 = make_float2(d[nt][2] * s1, d[nt][3] * s1);
        if (do_relu) {
            o0.x = fmaxf(o0.x, 0.f); o0.y = fmaxf(o0.y, 0.f);
            o1.x = fmaxf(o1.x, 0.f); o1.y = fmaxf(o1.y, 0.f);
        }
        *(float2*)&out[(size_t)row0 * HID + col] = o0;
        *(float2*)&out[(size_t)row1 * HID + col] = o1;
    }
}

// ---------------- tf32 fused layer-boundary matmul ------------------------
// hl_out = dinv_next * ( relu( (S*dinv_l + cbias_l) @ gcnW + gcnb ) @ linW )
__global__ __launch_bounds__(128) void fused_mm_tc(
    const float* __restrict__ S, const float* __restrict__ dinv_l,
    const float* __restrict__ cbias_l,
    const unsigned* __restrict__ gcnWtf, const float* __restrict__ gcnb,
    const unsigned* __restrict__ linWtf, const float* __restrict__ dinv_next,
    float* __restrict__ hl_out)
{
    __shared__ unsigned A_s[16 * SA];
    __shared__ unsigned B_s[32 * SB];
    const int t = threadIdx.x;
    const int base = blockIdx.x * 16;

#pragma unroll
    for (int it = 0; it < 4; it++) {
        int idx4 = t + it * 128;
        int row = idx4 >> 5, k4 = idx4 & 31;
        int grow = base + row;
        float4 v = *(const float4*)&S[(size_t)grow * HID + k4 * 4];
        float s = dinv_l[(size_t)grow * NL];
        v.x = fmaf(v.x, s, cbias_l[k4 * 4 + 0]);
        v.y = fmaf(v.y, s, cbias_l[k4 * 4 + 1]);
        v.z = fmaf(v.z, s, cbias_l[k4 * 4 + 2]);
        v.w = fmaf(v.w, s, cbias_l[k4 * 4 + 3]);
        A_s[row * SA + k4 * 4 + 0] = f2tf(v.x);
        A_s[row * SA + k4 * 4 + 1] = f2tf(v.y);
        A_s[row * SA + k4 * 4 + 2] = f2tf(v.z);
        A_s[row * SA + k4 * 4 + 3] = f2tf(v.w);
    }

    const int lane = t & 31, warp = t >> 5;
    const int g = lane >> 2, tg = lane & 3;
    const int nb = warp * 32;

    // stage 1: h = relu(tile @ gcnW + gcnb)
    float d[4][4];
#pragma unroll
    for (int nt = 0; nt < 4; nt++) {
        float c0 = gcnb[nb + nt * 8 + 2 * tg];
        float c1 = gcnb[nb + nt * 8 + 2 * tg + 1];
        d[nt][0] = c0; d[nt][1] = c1; d[nt][2] = c0; d[nt][3] = c1;
    }
    gemm_16x128(A_s, B_s, gcnWtf, d, t, lane, warp);
    __syncthreads();   // all warps done reading A_s before overwrite

    // write relu(h) as tf32 back into A_s
#pragma unroll
    for (int nt = 0; nt < 4; nt++) {
        int col = nb + nt * 8 + 2 * tg;
        A_s[g * SA + col]           = f2tf(fmaxf(d[nt][0], 0.f));
        A_s[g * SA + col + 1]       = f2tf(fmaxf(d[nt][1], 0.f));
        A_s[(g + 8) * SA + col]     = f2tf(fmaxf(d[nt][2], 0.f));
        A_s[(g + 8) * SA + col + 1] = f2tf(fmaxf(d[nt][3], 0.f));
    }

    // stage 2: hl = dinv_next * (h @ linW)
    float d2[4][4];
#pragma unroll
    for (int nt = 0; nt < 4; nt++) {
        d2[nt][0] = 0.f; d2[nt][1] = 0.f; d2[nt][2] = 0.f; d2[nt][3] = 0.f;
    }
    gemm_16x128(A_s, B_s, linWtf, d2, t, lane, warp);

    int row0 = base + g, row1 = row0 + 8;
    float s0 = dinv_next[(size_t)row0 * NL];
    float s1 = dinv_next[(size_t)row1 * NL];
#pragma unroll
    for (int nt = 0; nt < 4; nt++) {
        int col = nb + nt * 8 + 2 * tg;
        *(float2*)&hl_out[(size_t)row0 * HID + col] =
            make_float2(d2[nt][0] * s0, d2[nt][1] * s0);
        *(float2*)&hl_out[(size_t)row1 * HID + col] =
            make_float2(d2[nt][2] * s1, d2[nt][3] * s1);
    }
}

// ---------------- segment-mean pool -> g_cat left half --------------------
__global__ __launch_bounds__(128) void pool_seg(const int* __restrict__ batch)
{
    __shared__ int sbound[2];
    int g = blockIdx.x, t = threadIdx.x;
    if (t == 0) {
        int lo = 0, hi = NN;
        while (lo < hi) { int m = (lo + hi) >> 1; if (batch[m] < g) lo = m + 1; else hi = m; }
        sbound[0] = lo;
        int lo2 = lo; hi = NN;
        while (lo2 < hi) { int m = (lo2 + hi) >> 1; if (batch[m] < g + 1) lo2 = m + 1; else hi = m; }
        sbound[1] = lo2;
    }
    __syncthreads();
    int beg = sbound[0], end = sbound[1];
    float acc = 0.f;
    for (int n = beg; n < end; n++) acc += g_h[(size_t)n * HID + t];
    float cnt = (float)(end - beg);
    g_cat[(size_t)g * PIN + t] = acc / fmaxf(cnt, 1.f);
}

// ---------------- batched tail GEMM ---------------------------------------
__global__ __launch_bounds__(256) void dense_mr(
    const float* __restrict__ in, const float* __restrict__ W,
    const float* __restrict__ b, float* __restrict__ out,
    int K, int Nout, int out_stride, int do_relu)
{
    __shared__ float sin[32 * 129];
    const int t = threadIdx.x;
    const int rbase = blockIdx.y * 32;
    const int cbase = blockIdx.x * 64;
    const int cx = t & 15;
    const int ry = t >> 4;
    float acc[2][4];
    {
        float4 bv = *(const float4*)&b[cbase + cx * 4];
#pragma unroll
        for (int r = 0; r < 2; r++) {
            acc[r][0] = bv.x; acc[r][1] = bv.y; acc[r][2] = bv.z; acc[r][3] = bv.w;
        }
    }
    for (int k0 = 0; k0 < K; k0 += 128) {
        int klen = K - k0 < 128 ? K - k0 : 128;
#pragma unroll
        for (int it = 0; it < 4; it++) {
            int idx4 = t + it * 256;
            int row = idx4 >> 5;
            int k4 = idx4 & 31;
            float4 v = make_float4(0.f, 0.f, 0.f, 0.f);
            if (k4 * 4 < klen) {
                const float* src = &in[(size_t)(rbase + row) * K + k0 + k4 * 4];
                v.x = src[0];
                v.y = (k4 * 4 + 1 < klen) ? src[1] : 0.f;
                v.z = (k4 * 4 + 2 < klen) ? src[2] : 0.f;
                v.w = (k4 * 4 + 3 < klen) ? src[3] : 0.f;
            }
            sin[row * 129 + k4 * 4 + 0] = v.x;
            sin[row * 129 + k4 * 4 + 1] = v.y;
            sin[row * 129 + k4 * 4 + 2] = v.z;
            sin[row * 129 + k4 * 4 + 3] = v.w;
        }
        __syncthreads();
        for (int kk = 0; kk < klen; kk++) {
            float4 wv = *(const float4*)&W[(size_t)(k0 + kk) * Nout + cbase + cx * 4];
            float i0 = sin[(ry * 2 + 0) * 129 + kk];
            float i1 = sin[(ry * 2 + 1) * 129 + kk];
            acc[0][0] = fmaf(i0, wv.x, acc[0][0]); acc[0][1] = fmaf(i0, wv.y, acc[0][1]);
            acc[0][2] = fmaf(i0, wv.z, acc[0][2]); acc[0][3] = fmaf(i0, wv.w, acc[0][3]);
            acc[1][0] = fmaf(i1, wv.x, acc[1][0]); acc[1][1] = fmaf(i1, wv.y, acc[1][1]);
            acc[1][2] = fmaf(i1, wv.z, acc[1][2]); acc[1][3] = fmaf(i1, wv.w, acc[1][3]);
        }
        __syncthreads();
    }
#pragma unroll
    for (int r = 0; r < 2; r++) {
        float4 o = make_float4(acc[r][0], acc[r][1], acc[r][2], acc[r][3]);
        if (do_relu) {
            o.x = fmaxf(o.x, 0.f); o.y = fmaxf(o.y, 0.f);
            o.z = fmaxf(o.z, 0.f); o.w = fmaxf(o.w, 0.f);
        }
        *(float4*)&out[(size_t)(rbase + ry * 2 + r) * out_stride + cbase + cx * 4] = o;
    }
}

__global__ __launch_bounds__(128) void final_out(
    const float* __restrict__ W, const float* __restrict__ b,
    float* __restrict__ out)
{
    int g = blockIdx.x, t = threadIdx.x;
    float acc = 0.f;
    for (int k = t; k < PH; k += 128) acc = fmaf(g_p1[(size_t)g * PH + k], W[k], acc);
#pragma unroll
    for (int off = 16; off; off >>= 1) acc += __shfl_xor_sync(0xFFFFFFFFu, acc, off);
    __shared__ float s[4];
    if ((t & 31) == 0) s[t >> 5] = acc;
    __syncthreads();
    if (t == 0) out[g] = s[0] + s[1] + s[2] + s[3] + b[0];
}

// ---------------- launch --------------------------------------------------
extern "C" void kernel_launch(void* const* d_in, const int* in_sizes, int n_in,
                              void* d_out, int out_size)
{
    const float* x     = (const float*)d_in[0];
    const int*   ei    = (const int*)d_in[1];
    const float* ea    = (const float*)d_in[2];
    const int*   batch = (const int*)d_in[3];
    const float* mol   = (const float*)d_in[4];
    const float* clinW = (const float*)d_in[5];
    const float* cmW1  = (const float*)d_in[6];
    const float* cmb1  = (const float*)d_in[7];
    const float* cmW2  = (const float*)d_in[8];
    const float* cmb2  = (const float*)d_in[9];
    const float* cbias = (const float*)d_in[10];
    const float* gcnW  = (const float*)d_in[11];
    const float* gcnb  = (const float*)d_in[12];
    const float* mW0 = (const float*)d_in[13]; const float* mb0 = (const float*)d_in[14];
    const float* mW1 = (const float*)d_in[15]; const float* mb1 = (const float*)d_in[16];
    const float* mW2 = (const float*)d_in[17]; const float* mb2 = (const float*)d_in[18];
    const float* mW3 = (const float*)d_in[19]; const float* mb3 = (const float*)d_in[20];
    const float* pW0 = (const float*)d_in[21]; const float* pb0 = (const float*)d_in[22];
    const float* pW1 = (const float*)d_in[23]; const float* pb1 = (const float*)d_in[24];
    const float* oW  = (const float*)d_in[25]; const float* ob  = (const float*)d_in[26];
    float* out = (float*)d_out;

    const int* rowp = ei;
    const int* colp = ei + EE;

    static float *h_ptr = nullptr, *hl_ptr = nullptr, *out_ptr = nullptr;
    static float *w_ptr = nullptr, *dinv_ptr = nullptr;
    static unsigned *wtf_ptr = nullptr;
    static float *t0_p = nullptr, *t1_p = nullptr;
    static float *cat_p = nullptr, *p0_p = nullptr, *p1_p = nullptr;
    if (!h_ptr) {
        cudaGetSymbolAddress((void**)&h_ptr, g_h);
        cudaGetSymbolAddress((void**)&hl_ptr, g_hl);
        cudaGetSymbolAddress((void**)&out_ptr, g_out);
        cudaGetSymbolAddress((void**)&w_ptr, g_w);
        cudaGetSymbolAddress((void**)&dinv_ptr, g_dinv);
        cudaGetSymbolAddress((void**)&wtf_ptr, g_Wtf);
        cudaGetSymbolAddress((void**)&t0_p, g_t0);
        cudaGetSymbolAddress((void**)&t1_p, g_t1);
        cudaGetSymbolAddress((void**)&cat_p, g_cat);
        cudaGetSymbolAddress((void**)&p0_p, g_p0);
        cudaGetSymbolAddress((void**)&p1_p, g_p1);
    }

    const unsigned* lin_tf = wtf_ptr;
    const unsigned* gcn_tf = wtf_ptr + (size_t)NL * HID * HID;

    // weights -> tf32 (runs while CSR builds logically before mms)
    cvt_weights<<<(NL * HID * HID + 255) / 256, 256>>>(clinW, gcnW);

    // ---- CSR by destination ----
    const int nblk = (NN + 1023) / 1024;
    zero_cnt<<<(NN + 255) / 256, 256>>>();
    hist<<<(EE + 255) / 256, 256>>>(colp);
    blockscan<<<nblk, 1024>>>();
    midscan<<<1, 64>>>(nblk);
    addoff<<<(NN + 255) / 256, 256>>>();
    fill_csr<<<(EE + 255) / 256, 256>>>(rowp, colp);

    edge_mlp_all<<<(EE / 2 + 255) / 256, 256>>>(ea, cmW1, cmb1, cmW2, cmb2);
    deg_dinv<<<(NN + 255) / 256, 256>>>();

    const int mm_grid = NN / 16;   // 3125, exact

    // hl0 = dinv0 * (x @ linW0)
    node_mm_tc<<<mm_grid, 128>>>(x, lin_tf, nullptr, nullptr, nullptr,
                                 hl_ptr, dinv_ptr + 0, 0);
    for (int l = 0; l < NL; l++) {
        agg<<<(NN * 32 + 255) / 256, 256>>>(w_ptr + (size_t)l * EE);
        if (l < NL - 1) {
            fused_mm_tc<<<mm_grid, 128>>>(out_ptr, dinv_ptr + l,
                                          cbias + (size_t)l * HID,
                                          gcn_tf + (size_t)l * HID * HID,
                                          gcnb + (size_t)l * HID,
                                          lin_tf + (size_t)(l + 1) * HID * HID,
                                          dinv_ptr + (l + 1), hl_ptr);
        } else {
            node_mm_tc<<<mm_grid, 128>>>(out_ptr, gcn_tf + (size_t)l * HID * HID,
                                         dinv_ptr + l, cbias + (size_t)l * HID,
                                         gcnb + (size_t)l * HID, h_ptr, nullptr, 1);
        }
    }

    pool_seg<<<GG, 128>>>(batch);   // writes g_cat[:, 0:128]

    dense_mr<<<dim3(MH / 64, 8), 256>>>(mol,  mW0, mb0, t0_p, MINF, MH, MH, 1);
    dense_mr<<<dim3(MH / 64, 8), 256>>>(t0_p, mW1, mb1, t1_p, MH,   MH, MH, 1);
    dense_mr<<<dim3(MH / 64, 8), 256>>>(t1_p, mW2, mb2, t0_p, MH,   MH, MH, 1);
    dense_mr<<<dim3(MOUT / 64, 8), 256>>>(t0_p, mW3, mb3, cat_p + HID, MH, MOUT, PIN, 1);

    dense_mr<<<dim3(PH / 64, 8), 256>>>(cat_p, pW0, pb0, p0_p, PIN, PH, PH, 1);
    dense_mr<<<dim3(PH / 64, 8), 256>>>(p0_p,  pW1, pb1, p1_p, PH,  PH, PH, 1);
    final_out<<<GG, 128>>>(oW, ob, out);
}

// round 14
// speedup vs baseline: 1.4236x; 1.0745x over previous
#include <cuda_runtime.h>
#include <math.h>
#include <stdint.h>

#define NN     50000
#define EE     600000
#define GG     256
#define HID    128
#define EDIM   16
#define EH     64
#define NL     4
#define MINF   200
#define MH     256
#define MOUT   128
#define PH     512
#define PIN    (HID + MOUT)

#define SA 132          // A_s row stride — conflict-free fragment reads
#define SB 136          // B_s row stride — conflict-free fragment reads

typedef unsigned long long ull;

// ---------------- scratch (static device globals) -------------------------
__device__ float    g_w[NL * EE];       // [l][e] edge gates
__device__ float    g_dinv[NN * NL];    // [n][l]
__device__ float    g_h[NN * HID];
__device__ float    g_hl[NN * HID];
__device__ float    g_out[NN * HID];
__device__ unsigned g_Wtf[2 * NL * HID * HID];  // tf32 weights: [lin(0..3), gcn(0..3)]
__device__ int      g_cnt_csr[NN];
__device__ int      g_ptr[NN + 1];
__device__ int      g_cursor[NN];
__device__ int2     g_se[EE];
__device__ int      g_bsum[64];
__device__ int      g_boff[64];
__device__ float    g_t0[GG * MH];
__device__ float    g_t1[GG * MH];
__device__ float    g_cat[GG * PIN];
__device__ float    g_p0[GG * PH];
__device__ float    g_p1[GG * PH];

// ---------------- helpers -------------------------------------------------
__device__ __forceinline__ ull pack2(float a, float b)
{
    ull r; asm("mov.b64 %0, {%1, %2};" : "=l"(r) : "f"(a), "f"(b)); return r;
}
__device__ __forceinline__ void unpack2(ull p, float& a, float& b)
{
    asm("mov.b64 {%0, %1}, %2;" : "=f"(a), "=f"(b) : "l"(p));
}
#define FMA2(d, a, b, c) \
    asm("fma.rn.f32x2 %0, %1, %2, %3;" : "=l"(d) : "l"(a), "l"(b), "l"(c))

__device__ __forceinline__ unsigned f2tf(float f)
{
    unsigned u; asm("cvt.rna.tf32.f32 %0, %1;" : "=r"(u) : "f"(f)); return u;
}

__device__ __forceinline__ void mma_tf32(float* d,
    unsigned a0, unsigned a1, unsigned a2, unsigned a3,
    unsigned b0, unsigned b1)
{
    asm("mma.sync.aligned.m16n8k8.row.col.f32.tf32.tf32.f32 "
        "{%0,%1,%2,%3}, {%4,%5,%6,%7}, {%8,%9}, {%0,%1,%2,%3};"
        : "+f"(d[0]), "+f"(d[1]), "+f"(d[2]), "+f"(d[3])
        : "r"(a0), "r"(a1), "r"(a2), "r"(a3), "r"(b0), "r"(b1));
}

// 64x128 @ K=128 tf32 GEMM core; 256 threads (8 warps).
// warp w: cols (w&3)*32..+31, rows (w>>2)*32..+31 (two m16 fragments).
// B staged in 16-row chunks (fits static smem).
__device__ __forceinline__ void gemm_64x128(
    const unsigned* __restrict__ A_s, unsigned* __restrict__ B_s,
    const unsigned* __restrict__ W, float d[2][4][4], int t)
{
    const int lane = t & 31, w = t >> 5;
    const int g = lane >> 2, tg = lane & 3;
    const int nb = (w & 3) * 32;
    const int mb = (w >> 2) * 32;
#pragma unroll
    for (int kc = 0; kc < 8; kc++) {
        __syncthreads();
        // stage B chunk: k-rows kc*16..+15, all 128 cols (coalesced uint4)
#pragma unroll
        for (int it = 0; it < 2; it++) {
            int idx4 = t + it * 256;
            int r = idx4 >> 5, c4 = idx4 & 31;
            uint4 wv = *(const uint4*)&W[(size_t)(kc * 16 + r) * HID + c4 * 4];
            *(uint4*)&B_s[r * SB + c4 * 4] = wv;
        }
        __syncthreads();
#pragma unroll
        for (int ks = 0; ks < 2; ks++) {
            int K0 = kc * 16 + ks * 8;   // global k
            int kb = ks * 8;             // chunk-local k
            unsigned b[4][2];
#pragma unroll
            for (int nt = 0; nt < 4; nt++) {
                b[nt][0] = B_s[(kb + tg) * SB + nb + nt * 8 + g];
                b[nt][1] = B_s[(kb + tg + 4) * SB + nb + nt * 8 + g];
            }
#pragma unroll
            for (int mf = 0; mf < 2; mf++) {
                int rb = mb + mf * 16;
                unsigned a0 = A_s[(rb + g) * SA + K0 + tg];
                unsigned a1 = A_s[(rb + g + 8) * SA + K0 + tg];
                unsigned a2 = A_s[(rb + g) * SA + K0 + tg + 4];
                unsigned a3 = A_s[(rb + g + 8) * SA + K0 + tg + 4];
#pragma unroll
                for (int nt = 0; nt < 4; nt++)
                    mma_tf32(d[mf][nt], a0, a1, a2, a3, b[nt][0], b[nt][1]);
            }
        }
    }
}

// ---------------- weight conversion to tf32 -------------------------------
__global__ void cvt_weights(const float* __restrict__ linW,
                            const float* __restrict__ gcnW)
{
    int i = blockIdx.x * 256 + threadIdx.x;
    if (i < NL * HID * HID) {
        g_Wtf[i] = f2tf(linW[i]);
        g_Wtf[NL * HID * HID + i] = f2tf(gcnW[i]);
    }
}

// ---------------- CSR build -----------------------------------------------
__global__ void zero_cnt()
{
    int i = blockIdx.x * blockDim.x + threadIdx.x;
    if (i < NN) g_cnt_csr[i] = 0;
}

__global__ void hist(const int* __restrict__ colp)
{
    int e = blockIdx.x * blockDim.x + threadIdx.x;
    if (e < EE) atomicAdd(&g_cnt_csr[colp[e]], 1);
}

__global__ __launch_bounds__(1024) void blockscan()
{
    __shared__ int swsum[32];
    int t = threadIdx.x;
    int i = blockIdx.x * 1024 + t;
    int v = (i < NN) ? g_cnt_csr[i] : 0;
    int lane = t & 31, w = t >> 5;
    int incl = v;
#pragma unroll
    for (int off = 1; off < 32; off <<= 1) {
        int n = __shfl_up_sync(0xFFFFFFFFu, incl, off);
        if (lane >= off) incl += n;
    }
    if (lane == 31) swsum[w] = incl;
    __syncthreads();
    if (w == 0) {
        int s = swsum[lane];
        int si = s;
#pragma unroll
        for (int off = 1; off < 32; off <<= 1) {
            int n = __shfl_up_sync(0xFFFFFFFFu, si, off);
            if (lane >= off) si += n;
        }
        swsum[lane] = si - s;
        if (lane == 31 && blockIdx.x < 64) g_bsum[blockIdx.x] = si;
    }
    __syncthreads();
    int excl = incl - v + swsum[w];
    if (i < NN) g_ptr[i] = excl;
}

__global__ void midscan(int nblk)
{
    __shared__ int s[64];
    int t = threadIdx.x;
    int v = (t < nblk) ? g_bsum[t] : 0;
    s[t] = v;
    __syncthreads();
#pragma unroll
    for (int off = 1; off < 64; off <<= 1) {
        int add = (t >= off) ? s[t - off] : 0;
        __syncthreads();
        s[t] += add;
        __syncthreads();
    }
    g_boff[t] = s[t] - v;
}

__global__ void addoff()
{
    int i = blockIdx.x * blockDim.x + threadIdx.x;
    if (i < NN) {
        int p = g_ptr[i] + g_boff[i >> 10];
        g_ptr[i] = p;
        g_cursor[i] = p;
    }
    if (i == 0) g_ptr[NN] = EE;
}

__global__ void fill_csr(const int* __restrict__ rowp, const int* __restrict__ colp)
{
    int e = blockIdx.x * blockDim.x + threadIdx.x;
    if (e >= EE) return;
    int c = colp[e];
    int pos = atomicAdd(&g_cursor[c], 1);
    g_se[pos] = make_int2(rowp[e], e);
}

// ---------------- edge MLP: 2 edges/thread, f32x2 packed ------------------
__global__ __launch_bounds__(256) void edge_mlp_all(
    const float* __restrict__ ea, const float* __restrict__ mW1,
    const float* __restrict__ mb1, const float* __restrict__ mW2,
    const float* __restrict__ mb2)
{
    __shared__ ull   sW1p[NL][EH * EDIM];
    __shared__ ull   sb1p[NL][EH];
    __shared__ float sW2[NL][EH];
    __shared__ float sb2[NL];
    int t = threadIdx.x;
    for (int i = t; i < NL * EDIM * EH; i += 256) {
        int l = i / (EDIM * EH);
        int rem = i % (EDIM * EH);
        int k = rem / EH, j = rem % EH;
        float w = mW1[i];
        sW1p[l][j * EDIM + k] = pack2(w, w);
    }
    for (int i = t; i < NL * EH; i += 256) {
        float b = mb1[i];
        sb1p[i / EH][i % EH] = pack2(b, b);
        sW2[i / EH][i % EH] = mW2[i];
    }
    if (t < NL) sb2[t] = mb2[t];
    __syncthreads();

    int gid = blockIdx.x * 256 + t;
    if (gid >= EE / 2) return;
    int e0 = gid * 2;

    ull ap[EDIM];
    {
        const float4* p0 = (const float4*)(ea + (size_t)e0 * EDIM);
        const float4* p1 = (const float4*)(ea + (size_t)(e0 + 1) * EDIM);
#pragma unroll
        for (int q = 0; q < 4; q++) {
            float4 a0 = p0[q], a1 = p1[q];
            ap[q * 4 + 0] = pack2(a0.x, a1.x);
            ap[q * 4 + 1] = pack2(a0.y, a1.y);
            ap[q * 4 + 2] = pack2(a0.z, a1.z);
            ap[q * 4 + 3] = pack2(a0.w, a1.w);
        }
    }

#pragma unroll 1
    for (int l = 0; l < NL; l++) {
        float acc0 = sb2[l], acc1 = acc0;
#pragma unroll 2
        for (int j = 0; j < EH; j++) {
            const ull* wp = &sW1p[l][j * EDIM];
            ull sa = sb1p[l][j];
            ull sb = pack2(0.f, 0.f);
#pragma unroll
            for (int k = 0; k < EDIM; k += 2) {
                FMA2(sa, ap[k + 0], wp[k + 0], sa);
                FMA2(sb, ap[k + 1], wp[k + 1], sb);
            }
            float s0a, s1a, s0b, s1b;
            unpack2(sa, s0a, s1a);
            unpack2(sb, s0b, s1b);
            float w2 = sW2[l][j];
            acc0 = fmaf(fmaxf(s0a + s0b, 0.f), w2, acc0);
            acc1 = fmaf(fmaxf(s1a + s1b, 0.f), w2, acc1);
        }
        float2 o;
        o.x = 1.f / (1.f + __expf(-acc0));
        o.y = 1.f / (1.f + __expf(-acc1));
        ((float2*)(g_w + (size_t)l * EE))[gid] = o;
    }
}

// ---------------- degree + dinv via CSR -----------------------------------
__global__ void deg_dinv()
{
    int n = blockIdx.x * blockDim.x + threadIdx.x;
    if (n >= NN) return;
    int beg = g_ptr[n], end = g_ptr[n + 1];
    float d0 = 1.f, d1 = 1.f, d2 = 1.f, d3 = 1.f;
    for (int i = beg; i < end; i++) {
        int eid = g_se[i].y;
        d0 += g_w[0 * EE + eid];
        d1 += g_w[1 * EE + eid];
        d2 += g_w[2 * EE + eid];
        d3 += g_w[3 * EE + eid];
    }
    g_dinv[n * NL + 0] = rsqrtf(d0);
    g_dinv[n * NL + 1] = rsqrtf(d1);
    g_dinv[n * NL + 2] = rsqrtf(d2);
    g_dinv[n * NL + 3] = rsqrtf(d3);
}

// ---------------- gather-aggregate: 1 warp per node -----------------------
__global__ __launch_bounds__(256) void agg(const float* __restrict__ w)
{
    int gid = blockIdx.x * 256 + threadIdx.x;
    int n = gid >> 5;
    if (n >= NN) return;
    int lane = gid & 31;
    const float4* hlv = (const float4*)g_hl;
    float4 acc = hlv[(size_t)n * 32 + lane];
    int beg = g_ptr[n], end = g_ptr[n + 1];

    if (beg < end) {
        int2 se = __ldg(&g_se[beg]);
        float wt = __ldg(&w[se.y]);
        for (int i = beg; i < end; i++) {
            int2 se_n = make_int2(0, 0); float wt_n = 0.f;
            if (i + 1 < end) {
                se_n = __ldg(&g_se[i + 1]);
                wt_n = __ldg(&w[se_n.y]);
            }
            float4 v = hlv[(size_t)se.x * 32 + lane];
            acc.x = fmaf(wt, v.x, acc.x);
            acc.y = fmaf(wt, v.y, acc.y);
            acc.z = fmaf(wt, v.z, acc.z);
            acc.w = fmaf(wt, v.w, acc.w);
            se = se_n; wt = wt_n;
        }
    }
    ((float4*)g_out)[(size_t)n * 32 + lane] = acc;
}

// ---------------- tf32 node matmul: 64 rows x 128 cols, 256 thr -----------
__global__ __launch_bounds__(256) void node_mm_tc(
    const float* __restrict__ in, const unsigned* __restrict__ Wtf,
    const float* __restrict__ in_scale, const float* __restrict__ in_bias,
    const float* __restrict__ bias, float* __restrict__ out,
    const float* __restrict__ out_scale, int do_relu)
{
    __shared__ unsigned A_s[64 * SA];
    __shared__ unsigned B_s[16 * SB];
    const int t = threadIdx.x;
    const int base = blockIdx.x * 64;

    // stage A (fp32 -> tf32), 64 rows
#pragma unroll
    for (int it = 0; it < 8; it++) {
        int idx4 = t + it * 256;
        int row = idx4 >> 5, k4 = idx4 & 31;
        int grow = base + row;
        float4 v = make_float4(0.f, 0.f, 0.f, 0.f);
        if (grow < NN) {
            v = *(const float4*)&in[(size_t)grow * HID + k4 * 4];
            if (in_scale) {
                float s = in_scale[(size_t)grow * NL];
                v.x = fmaf(v.x, s, in_bias[k4 * 4 + 0]);
                v.y = fmaf(v.y, s, in_bias[k4 * 4 + 1]);
                v.z = fmaf(v.z, s, in_bias[k4 * 4 + 2]);
                v.w = fmaf(v.w, s, in_bias[k4 * 4 + 3]);
            }
        }
        A_s[row * SA + k4 * 4 + 0] = f2tf(v.x);
        A_s[row * SA + k4 * 4 + 1] = f2tf(v.y);
        A_s[row * SA + k4 * 4 + 2] = f2tf(v.z);
        A_s[row * SA + k4 * 4 + 3] = f2tf(v.w);
    }

    const int lane = t & 31, w = t >> 5;
    const int g = lane >> 2, tg = lane & 3;
    const int nb = (w & 3) * 32;
    const int mb = (w >> 2) * 32;

    float d[2][4][4];
#pragma unroll
    for (int mf = 0; mf < 2; mf++)
#pragma unroll
        for (int nt = 0; nt < 4; nt++) {
            float c0 = 0.f, c1 = 0.f;
            if (bias) {
                c0 = bias[nb + nt * 8 + 2 * tg];
                c1 = bias[nb + nt * 8 + 2 * tg + 1];
            }
            d[mf][nt][0] = c0; d[mf][nt][1] = c1;
            d[mf][nt][2] = c0; d[mf][nt][3] = c1;
        }

    gemm_64x128(A_s, B_s, Wtf, d, t);

#pragma unroll
    for (int mf = 0; mf < 2; mf++) {
        int row0 = base + mb + mf * 16 + g;
        int row1 = row0 + 8;
        float s0 = (row0 < NN && out_scale) ? out_scale[(size_t)row0 * NL] : 1.f;
        float s1 = (row1 < NN && out_scale) ? out_scale[(size_t)row1 * NL] : 1.f;
#pragma unroll
        for (int nt = 0; nt < 4; nt++) {
            int col = nb + nt * 8 + 2 * tg;
            float2 o0 = make_float2(d[mf][nt][0] * s0, d[mf][nt][1] * s0);
            float2 o1 = make_float2(d[mf][nt][2] * s1, d[mf][nt][3] * s1);
            if (do_relu) {
                o0.x = fmaxf(o0.x, 0.f); o0.y = fmaxf(o0.y, 0.f);
                o1.x = fmaxf(o1.x, 0.f); o1.y = fmaxf(o1.y, 0.f);
            }
            if (row0 < NN) *(float2*)&out[(size_t)row0 * HID + col] = o0;
            if (row1 < NN) *(float2*)&out[(size_t)row1 * HID + col] = o1;
        }
    }
}

// ---------------- tf32 fused layer-boundary matmul (64 rows) --------------
// hl_out = dinv_next * ( relu( (S*dinv_l + cbias_l) @ gcnW + gcnb ) @ linW )
__global__ __launch_bounds__(256) void fused_mm_tc(
    const float* __restrict__ S, const float* __restrict__ dinv_l,
    const float* __restrict__ cbias_l,
    const unsigned* __restrict__ gcnWtf, const float* __restrict__ gcnb,
    const unsigned* __restrict__ linWtf, const float* __restrict__ dinv_next,
    float* __restrict__ hl_out)
{
    __shared__ unsigned A_s[64 * SA];
    __shared__ unsigned B_s[16 * SB];
    const int t = threadIdx.x;
    const int base = blockIdx.x * 64;

#pragma unroll
    for (int it = 0; it < 8; it++) {
        int idx4 = t + it * 256;
        int row = idx4 >> 5, k4 = idx4 & 31;
        int grow = base + row;
        float4 v = make_float4(0.f, 0.f, 0.f, 0.f);
        if (grow < NN) {
            v = *(const float4*)&S[(size_t)grow * HID + k4 * 4];
            float s = dinv_l[(size_t)grow * NL];
            v.x = fmaf(v.x, s, cbias_l[k4 * 4 + 0]);
            v.y = fmaf(v.y, s, cbias_l[k4 * 4 + 1]);
            v.z = fmaf(v.z, s, cbias_l[k4 * 4 + 2]);
            v.w = fmaf(v.w, s, cbias_l[k4 * 4 + 3]);
        }
        A_s[row * SA + k4 * 4 + 0] = f2tf(v.x);
        A_s[row * SA + k4 * 4 + 1] = f2tf(v.y);
        A_s[row * SA + k4 * 4 + 2] = f2tf(v.z);
        A_s[row * SA + k4 * 4 + 3] = f2tf(v.w);
    }

    const int lane = t & 31, w = t >> 5;
    const int g = lane >> 2, tg = lane & 3;
    const int nb = (w & 3) * 32;
    const int mb = (w >> 2) * 32;

    // stage 1: h = relu(tile @ gcnW + gcnb)
    float d[2][4][4];
#pragma unroll
    for (int mf = 0; mf < 2; mf++)
#pragma unroll
        for (int nt = 0; nt < 4; nt++) {
            float c0 = gcnb[nb + nt * 8 + 2 * tg];
            float c1 = gcnb[nb + nt * 8 + 2 * tg + 1];
            d[mf][nt][0] = c0; d[mf][nt][1] = c1;
            d[mf][nt][2] = c0; d[mf][nt][3] = c1;
        }
    gemm_64x128(A_s, B_s, gcnWtf, d, t);
    __syncthreads();   // all warps done reading A_s before overwrite

    // write relu(h) as tf32 back into A_s (each warp: its rows x its cols)
#pragma unroll
    for (int mf = 0; mf < 2; mf++) {
        int r0 = mb + mf * 16 + g;
        int r1 = r0 + 8;
#pragma unroll
        for (int nt = 0; nt < 4; nt++) {
            int col = nb + nt * 8 + 2 * tg;
            A_s[r0 * SA + col]     = f2tf(fmaxf(d[mf][nt][0], 0.f));
            A_s[r0 * SA + col + 1] = f2tf(fmaxf(d[mf][nt][1], 0.f));
            A_s[r1 * SA + col]     = f2tf(fmaxf(d[mf][nt][2], 0.f));
            A_s[r1 * SA + col + 1] = f2tf(fmaxf(d[mf][nt][3], 0.f));
        }
    }

    // stage 2: hl = dinv_next * (h @ linW)
    float d2[2][4][4];
#pragma unroll
    for (int mf = 0; mf < 2; mf++)
#pragma unroll
        for (int nt = 0; nt < 4; nt++) {
            d2[mf][nt][0] = 0.f; d2[mf][nt][1] = 0.f;
            d2[mf][nt][2] = 0.f; d2[mf][nt][3] = 0.f;
        }
    gemm_64x128(A_s, B_s, linWtf, d2, t);

#pragma unroll
    for (int mf = 0; mf < 2; mf++) {
        int row0 = base + mb + mf * 16 + g;
        int row1 = row0 + 8;
        float s0 = (row0 < NN) ? dinv_next[(size_t)row0 * NL] : 0.f;
        float s1 = (row1 < NN) ? dinv_next[(size_t)row1 * NL] : 0.f;
#pragma unroll
        for (int nt = 0; nt < 4; nt++) {
            int col = nb + nt * 8 + 2 * tg;
            if (row0 < NN)
                *(float2*)&hl_out[(size_t)row0 * HID + col] =
                    make_float2(d2[mf][nt][0] * s0, d2[mf][nt][1] * s0);
            if (row1 < NN)
                *(float2*)&hl_out[(size_t)row1 * HID + col] =
                    make_float2(d2[mf][nt][2] * s1, d2[mf][nt][3] * s1);
        }
    }
}

// ---------------- segment-mean pool -> g_cat left half --------------------
__global__ __launch_bounds__(128) void pool_seg(const int* __restrict__ batch)
{
    __shared__ int sbound[2];
    int g = blockIdx.x, t = threadIdx.x;
    if (t == 0) {
        int lo = 0, hi = NN;
        while (lo < hi) { int m = (lo + hi) >> 1; if (batch[m] < g) lo = m + 1; else hi = m; }
        sbound[0] = lo;
        int lo2 = lo; hi = NN;
        while (lo2 < hi) { int m = (lo2 + hi) >> 1; if (batch[m] < g + 1) lo2 = m + 1; else hi = m; }
        sbound[1] = lo2;
    }
    __syncthreads();
    int beg = sbound[0], end = sbound[1];
    float acc = 0.f;
    for (int n = beg; n < end; n++) acc += g_h[(size_t)n * HID + t];
    float cnt = (float)(end - beg);
    g_cat[(size_t)g * PIN + t] = acc / fmaxf(cnt, 1.f);
}

// ---------------- batched tail GEMM ---------------------------------------
__global__ __launch_bounds__(256) void dense_mr(
    const float* __restrict__ in, const float* __restrict__ W,
    const float* __restrict__ b, float* __restrict__ out,
    int K, int Nout, int out_stride, int do_relu)
{
    __shared__ float sin[32 * 129];
    const int t = threadIdx.x;
    const int rbase = blockIdx.y * 32;
    const int cbase = blockIdx.x * 64;
    const int cx = t & 15;
    const int ry = t >> 4;
    float acc[2][4];
    {
        float4 bv = *(const float4*)&b[cbase + cx * 4];
#pragma unroll
        for (int r = 0; r < 2; r++) {
            acc[r][0] = bv.x; acc[r][1] = bv.y; acc[r][2] = bv.z; acc[r][3] = bv.w;
        }
    }
    for (int k0 = 0; k0 < K; k0 += 128) {
        int klen = K - k0 < 128 ? K - k0 : 128;
#pragma unroll
        for (int it = 0; it < 4; it++) {
            int idx4 = t + it * 256;
            int row = idx4 >> 5;
            int k4 = idx4 & 31;
            float4 v = make_float4(0.f, 0.f, 0.f, 0.f);
            if (k4 * 4 < klen) {
                const float* src = &in[(size_t)(rbase + row) * K + k0 + k4 * 4];
                v.x = src[0];
                v.y = (k4 * 4 + 1 < klen) ? src[1] : 0.f;
                v.z = (k4 * 4 + 2 < klen) ? src[2] : 0.f;
                v.w = (k4 * 4 + 3 < klen) ? src[3] : 0.f;
            }
            sin[row * 129 + k4 * 4 + 0] = v.x;
            sin[row * 129 + k4 * 4 + 1] = v.y;
            sin[row * 129 + k4 * 4 + 2] = v.z;
            sin[row * 129 + k4 * 4 + 3] = v.w;
        }
        __syncthreads();
        for (int kk = 0; kk < klen; kk++) {
            float4 wv = *(const float4*)&W[(size_t)(k0 + kk) * Nout + cbase + cx * 4];
            float i0 = sin[(ry * 2 + 0) * 129 + kk];
            float i1 = sin[(ry * 2 + 1) * 129 + kk];
            acc[0][0] = fmaf(i0, wv.x, acc[0][0]); acc[0][1] = fmaf(i0, wv.y, acc[0][1]);
            acc[0][2] = fmaf(i0, wv.z, acc[0][2]); acc[0][3] = fmaf(i0, wv.w, acc[0][3]);
            acc[1][0] = fmaf(i1, wv.x, acc[1][0]); acc[1][1] = fmaf(i1, wv.y, acc[1][1]);
            acc[1][2] = fmaf(i1, wv.z, acc[1][2]); acc[1][3] = fmaf(i1, wv.w, acc[1][3]);
        }
        __syncthreads();
    }
#pragma unroll
    for (int r = 0; r < 2; r++) {
        float4 o = make_float4(acc[r][0], acc[r][1], acc[r][2], acc[r][3]);
        if (do_relu) {
            o.x = fmaxf(o.x, 0.f); o.y = fmaxf(o.y, 0.f);
            o.z = fmaxf(o.z, 0.f); o.w = fmaxf(o.w, 0.f);
        }
        *(float4*)&out[(size_t)(rbase + ry * 2 + r) * out_stride + cbase + cx * 4] = o;
    }
}

__global__ __launch_bounds__(128) void final_out(
    const float* __restrict__ W, const float* __restrict__ b,
    float* __restrict__ out)
{
    int g = blockIdx.x, t = threadIdx.x;
    float acc = 0.f;
    for (int k = t; k < PH; k += 128) acc = fmaf(g_p1[(size_t)g * PH + k], W[k], acc);
#pragma unroll
    for (int off = 16; off; off >>= 1) acc += __shfl_xor_sync(0xFFFFFFFFu, acc, off);
    __shared__ float s[4];
    if ((t & 31) == 0) s[t >> 5] = acc;
    __syncthreads();
    if (t == 0) out[g] = s[0] + s[1] + s[2] + s[3] + b[0];
}

// ---------------- launch --------------------------------------------------
extern "C" void kernel_launch(void* const* d_in, const int* in_sizes, int n_in,
                              void* d_out, int out_size)
{
    const float* x     = (const float*)d_in[0];
    const int*   ei    = (const int*)d_in[1];
    const float* ea    = (const float*)d_in[2];
    const int*   batch = (const int*)d_in[3];
    const float* mol   = (const float*)d_in[4];
    const float* clinW = (const float*)d_in[5];
    const float* cmW1  = (const float*)d_in[6];
    const float* cmb1  = (const float*)d_in[7];
    const float* cmW2  = (const float*)d_in[8];
    const float* cmb2  = (const float*)d_in[9];
    const float* cbias = (const float*)d_in[10];
    const float* gcnW  = (const float*)d_in[11];
    const float* gcnb  = (const float*)d_in[12];
    const float* mW0 = (const float*)d_in[13]; const float* mb0 = (const float*)d_in[14];
    const float* mW1 = (const float*)d_in[15]; const float* mb1 = (const float*)d_in[16];
    const float* mW2 = (const float*)d_in[17]; const float* mb2 = (const float*)d_in[18];
    const float* mW3 = (const float*)d_in[19]; const float* mb3 = (const float*)d_in[20];
    const float* pW0 = (const float*)d_in[21]; const float* pb0 = (const float*)d_in[22];
    const float* pW1 = (const float*)d_in[23]; const float* pb1 = (const float*)d_in[24];
    const float* oW  = (const float*)d_in[25]; const float* ob  = (const float*)d_in[26];
    float* out = (float*)d_out;

    const int* rowp = ei;
    const int* colp = ei + EE;

    static float *h_ptr = nullptr, *hl_ptr = nullptr, *out_ptr = nullptr;
    static float *w_ptr = nullptr, *dinv_ptr = nullptr;
    static unsigned *wtf_ptr = nullptr;
    static float *t0_p = nullptr, *t1_p = nullptr;
    static float *cat_p = nullptr, *p0_p = nullptr, *p1_p = nullptr;
    if (!h_ptr) {
        cudaGetSymbolAddress((void**)&h_ptr, g_h);
        cudaGetSymbolAddress((void**)&hl_ptr, g_hl);
        cudaGetSymbolAddress((void**)&out_ptr, g_out);
        cudaGetSymbolAddress((void**)&w_ptr, g_w);
        cudaGetSymbolAddress((void**)&dinv_ptr, g_dinv);
        cudaGetSymbolAddress((void**)&wtf_ptr, g_Wtf);
        cudaGetSymbolAddress((void**)&t0_p, g_t0);
        cudaGetSymbolAddress((void**)&t1_p, g_t1);
        cudaGetSymbolAddress((void**)&cat_p, g_cat);
        cudaGetSymbolAddress((void**)&p0_p, g_p0);
        cudaGetSymbolAddress((void**)&p1_p, g_p1);
    }

    const unsigned* lin_tf = wtf_ptr;
    const unsigned* gcn_tf = wtf_ptr + (size_t)NL * HID * HID;

    cvt_weights<<<(NL * HID * HID + 255) / 256, 256>>>(clinW, gcnW);

    // ---- CSR by destination ----
    const int nblk = (NN + 1023) / 1024;
    zero_cnt<<<(NN + 255) / 256, 256>>>();
    hist<<<(EE + 255) / 256, 256>>>(colp);
    blockscan<<<nblk, 1024>>>();
    midscan<<<1, 64>>>(nblk);
    addoff<<<(NN + 255) / 256, 256>>>();
    fill_csr<<<(EE + 255) / 256, 256>>>(rowp, colp);

    edge_mlp_all<<<(EE / 2 + 255) / 256, 256>>>(ea, cmW1, cmb1, cmW2, cmb2);
    deg_dinv<<<(NN + 255) / 256, 256>>>();

    const int mm_grid = (NN + 63) / 64;   // 782

    // hl0 = dinv0 * (x @ linW0)
    node_mm_tc<<<mm_grid, 256>>>(x, lin_tf, nullptr, nullptr, nullptr,
                                 hl_ptr, dinv_ptr + 0, 0);
    for (int l = 0; l < NL; l++) {
        agg<<<(NN * 32 + 255) / 256, 256>>>(w_ptr + (size_t)l * EE);
        if (l < NL - 1) {
            fused_mm_tc<<<mm_grid, 256>>>(out_ptr, dinv_ptr + l,
                                          cbias + (size_t)l * HID,
                                          gcn_tf + (size_t)l * HID * HID,
                                          gcnb + (size_t)l * HID,
                                          lin_tf + (size_t)(l + 1) * HID * HID,
                                          dinv_ptr + (l + 1), hl_ptr);
        } else {
            node_mm_tc<<<mm_grid, 256>>>(out_ptr, gcn_tf + (size_t)l * HID * HID,
                                         dinv_ptr + l, cbias + (size_t)l * HID,
                                         gcnb + (size_t)l * HID, h_ptr, nullptr, 1);
        }
    }

    pool_seg<<<GG, 128>>>(batch);   // writes g_cat[:, 0:128]

    dense_mr<<<dim3(MH / 64, 8), 256>>>(mol,  mW0, mb0, t0_p, MINF, MH, MH, 1);
    dense_mr<<<dim3(MH / 64, 8), 256>>>(t0_p, mW1, mb1, t1_p, MH,   MH, MH, 1);
    dense_mr<<<dim3(MH / 64, 8), 256>>>(t1_p, mW2, mb2, t0_p, MH,   MH, MH, 1);
    dense_mr<<<dim3(MOUT / 64, 8), 256>>>(t0_p, mW3, mb3, cat_p + HID, MH, MOUT, PIN, 1);

    dense_mr<<<dim3(PH / 64, 8), 256>>>(cat_p, pW0, pb0, p0_p, PIN, PH, PH, 1);
    dense_mr<<<dim3(PH / 64, 8), 256>>>(p0_p,  pW1, pb1, p1_p, PH,  PH, PH, 1);
    final_out<<<GG, 128>>>(oW, ob, out);
}

// round 15
// speedup vs baseline: 1.4251x; 1.0011x over previous
#include <cuda_runtime.h>
#include <math.h>
#include <stdint.h>

#define NN     50000
#define EE     600000
#define GG     256
#define HID    128
#define EDIM   16
#define EH     64
#define NL     4
#define MINF   200
#define MH     256
#define MOUT   128
#define PH     512
#define PIN    (HID + MOUT)

#define SA 132          // A_s row stride — conflict-free fragment reads
#define SB 136          // B_s row stride — conflict-free fragment reads

typedef unsigned long long ull;

// ---------------- scratch (static device globals) -------------------------
__device__ float    g_w[NL * EE];       // [l][e] edge gates
__device__ float    g_dinv[NN * NL];    // [n][l]
__device__ float    g_h[NN * HID];
__device__ float    g_hl[NN * HID];
__device__ float    g_out[NN * HID];
__device__ unsigned g_Wtf[2 * NL * HID * HID];  // tf32 weights: [lin(0..3), gcn(0..3)]
__device__ int      g_cnt_csr[NN];
__device__ int      g_ptr[NN + 1];
__device__ int      g_cursor[NN];
__device__ int2     g_se[EE];
__device__ int      g_bsum[64];
__device__ int      g_boff[64];
__device__ float    g_t0[GG * MH];
__device__ float    g_t1[GG * MH];
__device__ float    g_cat[GG * PIN];
__device__ float    g_p0[GG * PH];
__device__ float    g_p1[GG * PH];

// ---------------- helpers -------------------------------------------------
__device__ __forceinline__ ull pack2(float a, float b)
{
    ull r; asm("mov.b64 %0, {%1, %2};" : "=l"(r) : "f"(a), "f"(b)); return r;
}
__device__ __forceinline__ void unpack2(ull p, float& a, float& b)
{
    asm("mov.b64 {%0, %1}, %2;" : "=f"(a), "=f"(b) : "l"(p));
}
#define FMA2(d, a, b, c) \
    asm("fma.rn.f32x2 %0, %1, %2, %3;" : "=l"(d) : "l"(a), "l"(b), "l"(c))

__device__ __forceinline__ unsigned f2tf(float f)
{
    unsigned u; asm("cvt.rna.tf32.f32 %0, %1;" : "=r"(u) : "f"(f)); return u;
}

__device__ __forceinline__ void mma_tf32(float* d,
    unsigned a0, unsigned a1, unsigned a2, unsigned a3,
    unsigned b0, unsigned b1)
{
    asm("mma.sync.aligned.m16n8k8.row.col.f32.tf32.tf32.f32 "
        "{%0,%1,%2,%3}, {%4,%5,%6,%7}, {%8,%9}, {%0,%1,%2,%3};"
        : "+f"(d[0]), "+f"(d[1]), "+f"(d[2]), "+f"(d[3])
        : "r"(a0), "r"(a1), "r"(a2), "r"(a3), "r"(b0), "r"(b1));
}

// 64x128 @ K=128 tf32 GEMM core; 256 threads (8 warps).
// warp w: cols (w&3)*32..+31, rows (w>>2)*32..+31 (two m16 fragments).
// B double-buffered in 8-k-row chunks; staging overlapped with MMA.
__device__ __forceinline__ void gemm_64x128(
    const unsigned* __restrict__ A_s, unsigned* __restrict__ B_s,  // B_s: 2*8*SB
    const unsigned* __restrict__ W, float d[2][4][4], int t)
{
    const int lane = t & 31, w = t >> 5;
    const int g = lane >> 2, tg = lane & 3;
    const int nb = (w & 3) * 32;
    const int mb = (w >> 2) * 32;
    const int sr = t >> 5;        // staging row 0..7
    const int sc4 = t & 31;       // staging col4 0..31

    // prologue: stage chunk 0
    {
        uint4 wv = *(const uint4*)&W[(size_t)sr * HID + sc4 * 4];
        *(uint4*)&B_s[sr * SB + sc4 * 4] = wv;
    }
    __syncthreads();

#pragma unroll
    for (int kc = 0; kc < 16; kc++) {
        unsigned* Bcur = B_s + (kc & 1) * 8 * SB;
        if (kc < 15) {
            unsigned* Bnext = B_s + ((kc + 1) & 1) * 8 * SB;
            uint4 wv = *(const uint4*)&W[(size_t)((kc + 1) * 8 + sr) * HID + sc4 * 4];
            *(uint4*)&Bnext[sr * SB + sc4 * 4] = wv;
        }
        int K0 = kc * 8;
        unsigned b[4][2];
#pragma unroll
        for (int nt = 0; nt < 4; nt++) {
            b[nt][0] = Bcur[tg * SB + nb + nt * 8 + g];
            b[nt][1] = Bcur[(tg + 4) * SB + nb + nt * 8 + g];
        }
#pragma unroll
        for (int mf = 0; mf < 2; mf++) {
            int rb = mb + mf * 16;
            unsigned a0 = A_s[(rb + g) * SA + K0 + tg];
            unsigned a1 = A_s[(rb + g + 8) * SA + K0 + tg];
            unsigned a2 = A_s[(rb + g) * SA + K0 + tg + 4];
            unsigned a3 = A_s[(rb + g + 8) * SA + K0 + tg + 4];
#pragma unroll
            for (int nt = 0; nt < 4; nt++)
                mma_tf32(d[mf][nt], a0, a1, a2, a3, b[nt][0], b[nt][1]);
        }
        __syncthreads();
    }
}

// ---------------- weight conversion to tf32 -------------------------------
__global__ void cvt_weights(const float* __restrict__ linW,
                            const float* __restrict__ gcnW)
{
    int i = blockIdx.x * 256 + threadIdx.x;
    if (i < NL * HID * HID) {
        g_Wtf[i] = f2tf(linW[i]);
        g_Wtf[NL * HID * HID + i] = f2tf(gcnW[i]);
    }
}

// ---------------- CSR build -----------------------------------------------
__global__ void zero_cnt()
{
    int i = blockIdx.x * blockDim.x + threadIdx.x;
    if (i < NN) g_cnt_csr[i] = 0;
}

__global__ void hist(const int* __restrict__ colp)
{
    int e = blockIdx.x * blockDim.x + threadIdx.x;
    if (e < EE) atomicAdd(&g_cnt_csr[colp[e]], 1);
}

__global__ __launch_bounds__(1024) void blockscan()
{
    __shared__ int swsum[32];
    int t = threadIdx.x;
    int i = blockIdx.x * 1024 + t;
    int v = (i < NN) ? g_cnt_csr[i] : 0;
    int lane = t & 31, w = t >> 5;
    int incl = v;
#pragma unroll
    for (int off = 1; off < 32; off <<= 1) {
        int n = __shfl_up_sync(0xFFFFFFFFu, incl, off);
        if (lane >= off) incl += n;
    }
    if (lane == 31) swsum[w] = incl;
    __syncthreads();
    if (w == 0) {
        int s = swsum[lane];
        int si = s;
#pragma unroll
        for (int off = 1; off < 32; off <<= 1) {
            int n = __shfl_up_sync(0xFFFFFFFFu, si, off);
            if (lane >= off) si += n;
        }
        swsum[lane] = si - s;
        if (lane == 31 && blockIdx.x < 64) g_bsum[blockIdx.x] = si;
    }
    __syncthreads();
    int excl = incl - v + swsum[w];
    if (i < NN) g_ptr[i] = excl;
}

__global__ void midscan(int nblk)
{
    __shared__ int s[64];
    int t = threadIdx.x;
    int v = (t < nblk) ? g_bsum[t] : 0;
    s[t] = v;
    __syncthreads();
#pragma unroll
    for (int off = 1; off < 64; off <<= 1) {
        int add = (t >= off) ? s[t - off] : 0;
        __syncthreads();
        s[t] += add;
        __syncthreads();
    }
    g_boff[t] = s[t] - v;
}

__global__ void addoff()
{
    int i = blockIdx.x * blockDim.x + threadIdx.x;
    if (i < NN) {
        int p = g_ptr[i] + g_boff[i >> 10];
        g_ptr[i] = p;
        g_cursor[i] = p;
    }
    if (i == 0) g_ptr[NN] = EE;
}

__global__ void fill_csr(const int* __restrict__ rowp, const int* __restrict__ colp)
{
    int e = blockIdx.x * blockDim.x + threadIdx.x;
    if (e >= EE) return;
    int c = colp[e];
    int pos = atomicAdd(&g_cursor[c], 1);
    g_se[pos] = make_int2(rowp[e], e);
}

// ---------------- edge MLP: 2 edges/thread, f32x2 packed ------------------
__global__ __launch_bounds__(256) void edge_mlp_all(
    const float* __restrict__ ea, const float* __restrict__ mW1,
    const float* __restrict__ mb1, const float* __restrict__ mW2,
    const float* __restrict__ mb2)
{
    __shared__ ull   sW1p[NL][EH * EDIM];
    __shared__ ull   sb1p[NL][EH];
    __shared__ float sW2[NL][EH];
    __shared__ float sb2[NL];
    int t = threadIdx.x;
    for (int i = t; i < NL * EDIM * EH; i += 256) {
        int l = i / (EDIM * EH);
        int rem = i % (EDIM * EH);
        int k = rem / EH, j = rem % EH;
        float w = mW1[i];
        sW1p[l][j * EDIM + k] = pack2(w, w);
    }
    for (int i = t; i < NL * EH; i += 256) {
        float b = mb1[i];
        sb1p[i / EH][i % EH] = pack2(b, b);
        sW2[i / EH][i % EH] = mW2[i];
    }
    if (t < NL) sb2[t] = mb2[t];
    __syncthreads();

    int gid = blockIdx.x * 256 + t;
    if (gid >= EE / 2) return;
    int e0 = gid * 2;

    ull ap[EDIM];
    {
        const float4* p0 = (const float4*)(ea + (size_t)e0 * EDIM);
        const float4* p1 = (const float4*)(ea + (size_t)(e0 + 1) * EDIM);
#pragma unroll
        for (int q = 0; q < 4; q++) {
            float4 a0 = p0[q], a1 = p1[q];
            ap[q * 4 + 0] = pack2(a0.x, a1.x);
            ap[q * 4 + 1] = pack2(a0.y, a1.y);
            ap[q * 4 + 2] = pack2(a0.z, a1.z);
            ap[q * 4 + 3] = pack2(a0.w, a1.w);
        }
    }

#pragma unroll 1
    for (int l = 0; l < NL; l++) {
        float acc0 = sb2[l], acc1 = acc0;
#pragma unroll 2
        for (int j = 0; j < EH; j++) {
            const ull* wp = &sW1p[l][j * EDIM];
            ull sa = sb1p[l][j];
            ull sb = pack2(0.f, 0.f);
#pragma unroll
            for (int k = 0; k < EDIM; k += 2) {
                FMA2(sa, ap[k + 0], wp[k + 0], sa);
                FMA2(sb, ap[k + 1], wp[k + 1], sb);
            }
            float s0a, s1a, s0b, s1b;
            unpack2(sa, s0a, s1a);
            unpack2(sb, s0b, s1b);
            float w2 = sW2[l][j];
            acc0 = fmaf(fmaxf(s0a + s0b, 0.f), w2, acc0);
            acc1 = fmaf(fmaxf(s1a + s1b, 0.f), w2, acc1);
        }
        float2 o;
        o.x = 1.f / (1.f + __expf(-acc0));
        o.y = 1.f / (1.f + __expf(-acc1));
        ((float2*)(g_w + (size_t)l * EE))[gid] = o;
    }
}

// ---------------- degree + dinv via CSR -----------------------------------
__global__ void deg_dinv()
{
    int n = blockIdx.x * blockDim.x + threadIdx.x;
    if (n >= NN) return;
    int beg = g_ptr[n], end = g_ptr[n + 1];
    float d0 = 1.f, d1 = 1.f, d2 = 1.f, d3 = 1.f;
    for (int i = beg; i < end; i++) {
        int eid = g_se[i].y;
        d0 += g_w[0 * EE + eid];
        d1 += g_w[1 * EE + eid];
        d2 += g_w[2 * EE + eid];
        d3 += g_w[3 * EE + eid];
    }
    g_dinv[n * NL + 0] = rsqrtf(d0);
    g_dinv[n * NL + 1] = rsqrtf(d1);
    g_dinv[n * NL + 2] = rsqrtf(d2);
    g_dinv[n * NL + 3] = rsqrtf(d3);
}

// ---------------- gather-aggregate: 1 warp per node, 4-way pipelined ------
__global__ __launch_bounds__(256) void agg(const float* __restrict__ w)
{
    int gid = blockIdx.x * 256 + threadIdx.x;
    int n = gid >> 5;
    if (n >= NN) return;
    int lane = gid & 31;
    const float4* hlv = (const float4*)g_hl;
    float4 acc = hlv[(size_t)n * 32 + lane];      // self-loop term = hl'[n]
    int beg = g_ptr[n], end = g_ptr[n + 1];

    int i = beg;
#pragma unroll 1
    for (; i + 4 <= end; i += 4) {
        int2 sa = __ldg(&g_se[i + 0]);
        int2 sb = __ldg(&g_se[i + 1]);
        int2 sc = __ldg(&g_se[i + 2]);
        int2 sd = __ldg(&g_se[i + 3]);
        float wa = __ldg(&w[sa.y]);
        float wb = __ldg(&w[sb.y]);
        float wc = __ldg(&w[sc.y]);
        float wd = __ldg(&w[sd.y]);
        float4 va = hlv[(size_t)sa.x * 32 + lane];
        float4 vb = hlv[(size_t)sb.x * 32 + lane];
        float4 vc = hlv[(size_t)sc.x * 32 + lane];
        float4 vd = hlv[(size_t)sd.x * 32 + lane];
        acc.x = fmaf(wa, va.x, acc.x); acc.y = fmaf(wa, va.y, acc.y);
        acc.z = fmaf(wa, va.z, acc.z); acc.w = fmaf(wa, va.w, acc.w);
        acc.x = fmaf(wb, vb.x, acc.x); acc.y = fmaf(wb, vb.y, acc.y);
        acc.z = fmaf(wb, vb.z, acc.z); acc.w = fmaf(wb, vb.w, acc.w);
        acc.x = fmaf(wc, vc.x, acc.x); acc.y = fmaf(wc, vc.y, acc.y);
        acc.z = fmaf(wc, vc.z, acc.z); acc.w = fmaf(wc, vc.w, acc.w);
        acc.x = fmaf(wd, vd.x, acc.x); acc.y = fmaf(wd, vd.y, acc.y);
        acc.z = fmaf(wd, vd.z, acc.z); acc.w = fmaf(wd, vd.w, acc.w);
    }
#pragma unroll 1
    for (; i < end; i++) {
        int2 se = __ldg(&g_se[i]);
        float wt = __ldg(&w[se.y]);
        float4 v = hlv[(size_t)se.x * 32 + lane];
        acc.x = fmaf(wt, v.x, acc.x);
        acc.y = fmaf(wt, v.y, acc.y);
        acc.z = fmaf(wt, v.z, acc.z);
        acc.w = fmaf(wt, v.w, acc.w);
    }
    ((float4*)g_out)[(size_t)n * 32 + lane] = acc;
}

// ---------------- tf32 node matmul: 64 rows x 128 cols, 256 thr -----------
__global__ __launch_bounds__(256) void node_mm_tc(
    const float* __restrict__ in, const unsigned* __restrict__ Wtf,
    const float* __restrict__ in_scale, const float* __restrict__ in_bias,
    const float* __restrict__ bias, float* __restrict__ out,
    const float* __restrict__ out_scale, int do_relu)
{
    __shared__ unsigned A_s[64 * SA];
    __shared__ unsigned B_s[2 * 8 * SB];
    const int t = threadIdx.x;
    const int base = blockIdx.x * 64;

    // stage A (fp32 -> tf32), 64 rows
#pragma unroll
    for (int it = 0; it < 8; it++) {
        int idx4 = t + it * 256;
        int row = idx4 >> 5, k4 = idx4 & 31;
        int grow = base + row;
        float4 v = make_float4(0.f, 0.f, 0.f, 0.f);
        if (grow < NN) {
            v = *(const float4*)&in[(size_t)grow * HID + k4 * 4];
            if (in_scale) {
                float s = in_scale[(size_t)grow * NL];
                v.x = fmaf(v.x, s, in_bias[k4 * 4 + 0]);
                v.y = fmaf(v.y, s, in_bias[k4 * 4 + 1]);
                v.z = fmaf(v.z, s, in_bias[k4 * 4 + 2]);
                v.w = fmaf(v.w, s, in_bias[k4 * 4 + 3]);
            }
        }
        A_s[row * SA + k4 * 4 + 0] = f2tf(v.x);
        A_s[row * SA + k4 * 4 + 1] = f2tf(v.y);
        A_s[row * SA + k4 * 4 + 2] = f2tf(v.z);
        A_s[row * SA + k4 * 4 + 3] = f2tf(v.w);
    }
    __syncthreads();

    const int lane = t & 31, w = t >> 5;
    const int g = lane >> 2, tg = lane & 3;
    const int nb = (w & 3) * 32;
    const int mb = (w >> 2) * 32;

    float d[2][4][4];
#pragma unroll
    for (int mf = 0; mf < 2; mf++)
#pragma unroll
        for (int nt = 0; nt < 4; nt++) {
            float c0 = 0.f, c1 = 0.f;
            if (bias) {
                c0 = bias[nb + nt * 8 + 2 * tg];
                c1 = bias[nb + nt * 8 + 2 * tg + 1];
            }
            d[mf][nt][0] = c0; d[mf][nt][1] = c1;
            d[mf][nt][2] = c0; d[mf][nt][3] = c1;
        }

    gemm_64x128(A_s, B_s, Wtf, d, t);

#pragma unroll
    for (int mf = 0; mf < 2; mf++) {
        int row0 = base + mb + mf * 16 + g;
        int row1 = row0 + 8;
        float s0 = (row0 < NN && out_scale) ? out_scale[(size_t)row0 * NL] : 1.f;
        float s1 = (row1 < NN && out_scale) ? out_scale[(size_t)row1 * NL] : 1.f;
#pragma unroll
        for (int nt = 0; nt < 4; nt++) {
            int col = nb + nt * 8 + 2 * tg;
            float2 o0 = make_float2(d[mf][nt][0] * s0, d[mf][nt][1] * s0);
            float2 o1 = make_float2(d[mf][nt][2] * s1, d[mf][nt][3] * s1);
            if (do_relu) {
                o0.x = fmaxf(o0.x, 0.f); o0.y = fmaxf(o0.y, 0.f);
                o1.x = fmaxf(o1.x, 0.f); o1.y = fmaxf(o1.y, 0.f);
            }
            if (row0 < NN) *(float2*)&out[(size_t)row0 * HID + col] = o0;
            if (row1 < NN) *(float2*)&out[(size_t)row1 * HID + col] = o1;
        }
    }
}

// ---------------- tf32 fused layer-boundary matmul (64 rows) --------------
// hl_out = dinv_next * ( relu( (S*dinv_l + cbias_l) @ gcnW + gcnb ) @ linW )
__global__ __launch_bounds__(256) void fused_mm_tc(
    const float* __restrict__ S, const float* __restrict__ dinv_l,
    const float* __restrict__ cbias_l,
    const unsigned* __restrict__ gcnWtf, const float* __restrict__ gcnb,
    const unsigned* __restrict__ linWtf, const float* __restrict__ dinv_next,
    float* __restrict__ hl_out)
{
    __shared__ unsigned A_s[64 * SA];
    __shared__ unsigned B_s[2 * 8 * SB];
    const int t = threadIdx.x;
    const int base = blockIdx.x * 64;

#pragma unroll
    for (int it = 0; it < 8; it++) {
        int idx4 = t + it * 256;
        int row = idx4 >> 5, k4 = idx4 & 31;
        int grow = base + row;
        float4 v = make_float4(0.f, 0.f, 0.f, 0.f);
        if (grow < NN) {
            v = *(const float4*)&S[(size_t)grow * HID + k4 * 4];
            float s = dinv_l[(size_t)grow * NL];
            v.x = fmaf(v.x, s, cbias_l[k4 * 4 + 0]);
            v.y = fmaf(v.y, s, cbias_l[k4 * 4 + 1]);
            v.z = fmaf(v.z, s, cbias_l[k4 * 4 + 2]);
            v.w = fmaf(v.w, s, cbias_l[k4 * 4 + 3]);
        }
        A_s[row * SA + k4 * 4 + 0] = f2tf(v.x);
        A_s[row * SA + k4 * 4 + 1] = f2tf(v.y);
        A_s[row * SA + k4 * 4 + 2] = f2tf(v.z);
        A_s[row * SA + k4 * 4 + 3] = f2tf(v.w);
    }
    __syncthreads();

    const int lane = t & 31, w = t >> 5;
    const int g = lane >> 2, tg = lane & 3;
    const int nb = (w & 3) * 32;
    const int mb = (w >> 2) * 32;

    // stage 1: h = relu(tile @ gcnW + gcnb)
    float d[2][4][4];
#pragma unroll
    for (int mf = 0; mf < 2; mf++)
#pragma unroll
        for (int nt = 0; nt < 4; nt++) {
            float c0 = gcnb[nb + nt * 8 + 2 * tg];
            float c1 = gcnb[nb + nt * 8 + 2 * tg + 1];
            d[mf][nt][0] = c0; d[mf][nt][1] = c1;
            d[mf][nt][2] = c0; d[mf][nt][3] = c1;
        }
    gemm_64x128(A_s, B_s, gcnWtf, d, t);
    __syncthreads();   // all warps done reading A_s before overwrite

    // write relu(h) as tf32 back into A_s (each warp: its rows x its cols)
#pragma unroll
    for (int mf = 0; mf < 2; mf++) {
        int r0 = mb + mf * 16 + g;
        int r1 = r0 + 8;
#pragma unroll
        for (int nt = 0; nt < 4; nt++) {
            int col = nb + nt * 8 + 2 * tg;
            A_s[r0 * SA + col]     = f2tf(fmaxf(d[mf][nt][0], 0.f));
            A_s[r0 * SA + col + 1] = f2tf(fmaxf(d[mf][nt][1], 0.f));
            A_s[r1 * SA + col]     = f2tf(fmaxf(d[mf][nt][2], 0.f));
            A_s[r1 * SA + col + 1] = f2tf(fmaxf(d[mf][nt][3], 0.f));
        }
    }
    __syncthreads();

    // stage 2: hl = dinv_next * (h @ linW)
    float d2[2][4][4];
#pragma unroll
    for (int mf = 0; mf < 2; mf++)
#pragma unroll
        for (int nt = 0; nt < 4; nt++) {
            d2[mf][nt][0] = 0.f; d2[mf][nt][1] = 0.f;
            d2[mf][nt][2] = 0.f; d2[mf][nt][3] = 0.f;
        }
    gemm_64x128(A_s, B_s, linWtf, d2, t);

#pragma unroll
    for (int mf = 0; mf < 2; mf++) {
        int row0 = base + mb + mf * 16 + g;
        int row1 = row0 + 8;
        float s0 = (row0 < NN) ? dinv_next[(size_t)row0 * NL] : 0.f;
        float s1 = (row1 < NN) ? dinv_next[(size_t)row1 * NL] : 0.f;
#pragma unroll
        for (int nt = 0; nt < 4; nt++) {
            int col = nb + nt * 8 + 2 * tg;
            if (row0 < NN)
                *(float2*)&hl_out[(size_t)row0 * HID + col] =
                    make_float2(d2[mf][nt][0] * s0, d2[mf][nt][1] * s0);
            if (row1 < NN)
                *(float2*)&hl_out[(size_t)row1 * HID + col] =
                    make_float2(d2[mf][nt][2] * s1, d2[mf][nt][3] * s1);
        }
    }
}

// ---------------- segment-mean pool -> g_cat left half --------------------
__global__ __launch_bounds__(128) void pool_seg(const int* __restrict__ batch)
{
    __shared__ int sbound[2];
    int g = blockIdx.x, t = threadIdx.x;
    if (t == 0) {
        int lo = 0, hi = NN;
        while (lo < hi) { int m = (lo + hi) >> 1; if (batch[m] < g) lo = m + 1; else hi = m; }
        sbound[0] = lo;
        int lo2 = lo; hi = NN;
        while (lo2 < hi) { int m = (lo2 + hi) >> 1; if (batch[m] < g + 1) lo2 = m + 1; else hi = m; }
        sbound[1] = lo2;
    }
    __syncthreads();
    int beg = sbound[0], end = sbound[1];
    float acc = 0.f;
    for (int n = beg; n < end; n++) acc += g_h[(size_t)n * HID + t];
    float cnt = (float)(end - beg);
    g_cat[(size_t)g * PIN + t] = acc / fmaxf(cnt, 1.f);
}

// ---------------- batched tail GEMM ---------------------------------------
__global__ __launch_bounds__(256) void dense_mr(
    const float* __restrict__ in, const float* __restrict__ W,
    const float* __restrict__ b, float* __restrict__ out,
    int K, int Nout, int out_stride, int do_relu)
{
    __shared__ float sin[32 * 129];
    const int t = threadIdx.x;
    const int rbase = blockIdx.y * 32;
    const int cbase = blockIdx.x * 64;
    const int cx = t & 15;
    const int ry = t >> 4;
    float acc[2][4];
    {
        float4 bv = *(const float4*)&b[cbase + cx * 4];
#pragma unroll
        for (int r = 0; r < 2; r++) {
            acc[r][0] = bv.x; acc[r][1] = bv.y; acc[r][2] = bv.z; acc[r][3] = bv.w;
        }
    }
    for (int k0 = 0; k0 < K; k0 += 128) {
        int klen = K - k0 < 128 ? K - k0 : 128;
#pragma unroll
        for (int it = 0; it < 4; it++) {
            int idx4 = t + it * 256;
            int row = idx4 >> 5;
            int k4 = idx4 & 31;
            float4 v = make_float4(0.f, 0.f, 0.f, 0.f);
            if (k4 * 4 < klen) {
                const float* src = &in[(size_t)(rbase + row) * K + k0 + k4 * 4];
                v.x = src[0];
                v.y = (k4 * 4 + 1 < klen) ? src[1] : 0.f;
                v.z = (k4 * 4 + 2 < klen) ? src[2] : 0.f;
                v.w = (k4 * 4 + 3 < klen) ? src[3] : 0.f;
            }
            sin[row * 129 + k4 * 4 + 0] = v.x;
            sin[row * 129 + k4 * 4 + 1] = v.y;
            sin[row * 129 + k4 * 4 + 2] = v.z;
            sin[row * 129 + k4 * 4 + 3] = v.w;
        }
        __syncthreads();
        for (int kk = 0; kk < klen; kk++) {
            float4 wv = *(const float4*)&W[(size_t)(k0 + kk) * Nout + cbase + cx * 4];
            float i0 = sin[(ry * 2 + 0) * 129 + kk];
            float i1 = sin[(ry * 2 + 1) * 129 + kk];
            acc[0][0] = fmaf(i0, wv.x, acc[0][0]); acc[0][1] = fmaf(i0, wv.y, acc[0][1]);
            acc[0][2] = fmaf(i0, wv.z, acc[0][2]); acc[0][3] = fmaf(i0, wv.w, acc[0][3]);
            acc[1][0] = fmaf(i1, wv.x, acc[1][0]); acc[1][1] = fmaf(i1, wv.y, acc[1][1]);
            acc[1][2] = fmaf(i1, wv.z, acc[1][2]); acc[1][3] = fmaf(i1, wv.w, acc[1][3]);
        }
        __syncthreads();
    }
#pragma unroll
    for (int r = 0; r < 2; r++) {
        float4 o = make_float4(acc[r][0], acc[r][1], acc[r][2], acc[r][3]);
        if (do_relu) {
            o.x = fmaxf(o.x, 0.f); o.y = fmaxf(o.y, 0.f);
            o.z = fmaxf(o.z, 0.f); o.w = fmaxf(o.w, 0.f);
        }
        *(float4*)&out[(size_t)(rbase + ry * 2 + r) * out_stride + cbase + cx * 4] = o;
    }
}

__global__ __launch_bounds__(128) void final_out(
    const float* __restrict__ W, const float* __restrict__ b,
    float* __restrict__ out)
{
    int g = blockIdx.x, t = threadIdx.x;
    float acc = 0.f;
    for (int k = t; k < PH; k += 128) acc = fmaf(g_p1[(size_t)g * PH + k], W[k], acc);
#pragma unroll
    for (int off = 16; off; off >>= 1) acc += __shfl_xor_sync(0xFFFFFFFFu, acc, off);
    __shared__ float s[4];
    if ((t & 31) == 0) s[t >> 5] = acc;
    __syncthreads();
    if (t == 0) out[g] = s[0] + s[1] + s[2] + s[3] + b[0];
}

// ---------------- launch --------------------------------------------------
extern "C" void kernel_launch(void* const* d_in, const int* in_sizes, int n_in,
                              void* d_out, int out_size)
{
    const float* x     = (const float*)d_in[0];
    const int*   ei    = (const int*)d_in[1];
    const float* ea    = (const float*)d_in[2];
    const int*   batch = (const int*)d_in[3];
    const float* mol   = (const float*)d_in[4];
    const float* clinW = (const float*)d_in[5];
    const float* cmW1  = (const float*)d_in[6];
    const float* cmb1  = (const float*)d_in[7];
    const float* cmW2  = (const float*)d_in[8];
    const float* cmb2  = (const float*)d_in[9];
    const float* cbias = (const float*)d_in[10];
    const float* gcnW  = (const float*)d_in[11];
    const float* gcnb  = (const float*)d_in[12];
    const float* mW0 = (const float*)d_in[13]; const float* mb0 = (const float*)d_in[14];
    const float* mW1 = (const float*)d_in[15]; const float* mb1 = (const float*)d_in[16];
    const float* mW2 = (const float*)d_in[17]; const float* mb2 = (const float*)d_in[18];
    const float* mW3 = (const float*)d_in[19]; const float* mb3 = (const float*)d_in[20];
    const float* pW0 = (const float*)d_in[21]; const float* pb0 = (const float*)d_in[22];
    const float* pW1 = (const float*)d_in[23]; const float* pb1 = (const float*)d_in[24];
    const float* oW  = (const float*)d_in[25]; const float* ob  = (const float*)d_in[26];
    float* out = (float*)d_out;

    const int* rowp = ei;
    const int* colp = ei + EE;

    static float *h_ptr = nullptr, *hl_ptr = nullptr, *out_ptr = nullptr;
    static float *w_ptr = nullptr, *dinv_ptr = nullptr;
    static unsigned *wtf_ptr = nullptr;
    static float *t0_p = nullptr, *t1_p = nullptr;
    static float *cat_p = nullptr, *p0_p = nullptr, *p1_p = nullptr;
    if (!h_ptr) {
        cudaGetSymbolAddress((void**)&h_ptr, g_h);
        cudaGetSymbolAddress((void**)&hl_ptr, g_hl);
        cudaGetSymbolAddress((void**)&out_ptr, g_out);
        cudaGetSymbolAddress((void**)&w_ptr, g_w);
        cudaGetSymbolAddress((void**)&dinv_ptr, g_dinv);
        cudaGetSymbolAddress((void**)&wtf_ptr, g_Wtf);
        cudaGetSymbolAddress((void**)&t0_p, g_t0);
        cudaGetSymbolAddress((void**)&t1_p, g_t1);
        cudaGetSymbolAddress((void**)&cat_p, g_cat);
        cudaGetSymbolAddress((void**)&p0_p, g_p0);
        cudaGetSymbolAddress((void**)&p1_p, g_p1);
    }

    const unsigned* lin_tf = wtf_ptr;
    const unsigned* gcn_tf = wtf_ptr + (size_t)NL * HID * HID;

    cvt_weights<<<(NL * HID * HID + 255) / 256, 256>>>(clinW, gcnW);

    // ---- CSR by destination ----
    const int nblk = (NN + 1023) / 1024;
    zero_cnt<<<(NN + 255) / 256, 256>>>();
    hist<<<(EE + 255) / 256, 256>>>(colp);
    blockscan<<<nblk, 1024>>>();
    midscan<<<1, 64>>>(nblk);
    addoff<<<(NN + 255) / 256, 256>>>();
    fill_csr<<<(EE + 255) / 256, 256>>>(rowp, colp);

    edge_mlp_all<<<(EE / 2 + 255) / 256, 256>>>(ea, cmW1, cmb1, cmW2, cmb2);
    deg_dinv<<<(NN + 255) / 256, 256>>>();

    const int mm_grid = (NN + 63) / 64;   // 782

    // hl0 = dinv0 * (x @ linW0)
    node_mm_tc<<<mm_grid, 256>>>(x, lin_tf, nullptr, nullptr, nullptr,
                                 hl_ptr, dinv_ptr + 0, 0);
    for (int l = 0; l < NL; l++) {
        agg<<<(NN * 32 + 255) / 256, 256>>>(w_ptr + (size_t)l * EE);
        if (l < NL - 1) {
            fused_mm_tc<<<mm_grid, 256>>>(out_ptr, dinv_ptr + l,
                                          cbias + (size_t)l * HID,
                                          gcn_tf + (size_t)l * HID * HID,
                                          gcnb + (size_t)l * HID,
                                          lin_tf + (size_t)(l + 1) * HID * HID,
                                          dinv_ptr + (l + 1), hl_ptr);
        } else {
            node_mm_tc<<<mm_grid, 256>>>(out_ptr, gcn_tf + (size_t)l * HID * HID,
                                         dinv_ptr + l, cbias + (size_t)l * HID,
                                         gcnb + (size_t)l * HID, h_ptr, nullptr, 1);
        }
    }

    pool_seg<<<GG, 128>>>(batch);   // writes g_cat[:, 0:128]

    dense_mr<<<dim3(MH / 64, 8), 256>>>(mol,  mW0, mb0, t0_p, MINF, MH, MH, 1);
    dense_mr<<<dim3(MH / 64, 8), 256>>>(t0_p, mW1, mb1, t1_p, MH,   MH, MH, 1);
    dense_mr<<<dim3(MH / 64, 8), 256>>>(t1_p, mW2, mb2, t0_p, MH,   MH, MH, 1);
    dense_mr<<<dim3(MOUT / 64, 8), 256>>>(t0_p, mW3, mb3, cat_p + HID, MH, MOUT, PIN, 1);

    dense_mr<<<dim3(PH / 64, 8), 256>>>(cat_p, pW0, pb0, p0_p, PIN, PH, PH, 1);
    dense_mr<<<dim3(PH / 64, 8), 256>>>(p0_p,  pW1, pb1, p1_p, PH,  PH, PH, 1);
    final_out<<<GG, 128>>>(oW, ob, out);
}